// round 5
// baseline (speedup 1.0000x reference)
#include <cuda_runtime.h>
#include <cstdint>
#include <math.h>

#define BB   8
#define NN   4096
#define HID  64
#define JJ   128
#define CAP  96
#define NROWS (BB*NN)   // 32768

// ---- scratch (device globals; no allocation allowed) ----
__device__ int   g_cnt[NROWS];
__device__ int   g_idx[(size_t)NROWS * CAP];   // packed: col | (val==2 ? 0x80000000 : 0)
__device__ float g_h1[(size_t)NROWS * HID];    // 8 MB
__device__ float g_h2[(size_t)NROWS * HID];    // 8 MB
__device__ float g_gge[BB * HID];              // global graph embedding accumulator
__device__ float g_scores[BB * JJ];            // actor scores before softmax
__device__ int   g_done[BB];                   // per-batch completion counters

// ============================================================================
// Kernel 1: stream adj once. Warp-per-row, group-skip nonzero detection,
// 8 uint4 loads in flight. 16 rows / 512-thread block + fused GIN0 MLP.
// ============================================================================
__global__ __launch_bounds__(512) void k1_scan(
    const float* __restrict__ adj, const float* __restrict__ feat,
    const float* __restrict__ w1, const float* __restrict__ b1,
    const float* __restrict__ w2, const float* __restrict__ b2)
{
    __shared__ float s_w2[HID * HID];   // 16 KB
    __shared__ float s_w1[2 * HID];
    __shared__ float s_b1[HID], s_b2[HID];
    __shared__ float s_p[16][2];
    __shared__ float s_z[16][HID];

    const int tid  = threadIdx.x;
    const int w    = tid >> 5;
    const int lane = tid & 31;
    const unsigned lmask = (1u << lane) - 1u;

    for (int i = tid; i < HID * HID; i += 512) s_w2[i] = w2[i];
    if (tid < 2 * HID) s_w1[tid] = w1[tid];
    if (tid < HID) { s_b1[tid] = b1[tid]; s_b2[tid] = b2[tid]; }
    if (blockIdx.x == 0) {              // zero accumulators for k2/k3
        if (tid < BB * HID) g_gge[tid] = 0.f;
        if (tid < BB) g_done[tid] = 0;
    }

    // ---- Phase A: each warp scans one full adjacency row ----
    const int r = blockIdx.x * 16 + w;
    const int b = r >> 12;
    const uint4* __restrict__ arow = (const uint4*)(adj + (size_t)r * NN);  // 1024
    const float2* __restrict__ f2p = (const float2*)feat + (size_t)b * NN;
    int* __restrict__ irow = g_idx + (size_t)r * CAP;

    float p0 = 0.f, p1 = 0.f;
    int base = 0;

#define PROC_ELEM(bits, jj) do {                                           \
        const bool nz = (bits) != 0u;                                      \
        const unsigned m = __ballot_sync(0xffffffffu, nz);                 \
        if (nz) {                                                          \
            const int off = base + __popc(m & lmask);                      \
            const bool two = ((bits) == 0x40000000u);                      \
            if (off < CAP) irow[off] = (jj) | (two ? 0x80000000 : 0);      \
            const float2 f = f2p[(jj)];                                    \
            const float sv = two ? 2.f : 1.f;                              \
            p0 += sv * f.x; p1 += sv * f.y;                                \
        }                                                                  \
        base += __popc(m);                                                 \
    } while (0)

    #pragma unroll 1
    for (int it = 0; it < 4; it++) {
        uint4 v[8];
        #pragma unroll
        for (int k = 0; k < 8; k++)
            v[k] = arow[it * 256 + lane + 32 * k];
        #pragma unroll
        for (int k = 0; k < 8; k++) {
            const unsigned any = v[k].x | v[k].y | v[k].z | v[k].w;
            const unsigned grp = __ballot_sync(0xffffffffu, any != 0u);
            if (grp) {   // warp-uniform, rare
                const int jb = (it * 256 + lane + 32 * k) * 4;
                PROC_ELEM(v[k].x, jb + 0);
                PROC_ELEM(v[k].y, jb + 1);
                PROC_ELEM(v[k].z, jb + 2);
                PROC_ELEM(v[k].w, jb + 3);
            }
        }
    }
#undef PROC_ELEM

    #pragma unroll
    for (int o = 16; o > 0; o >>= 1) {
        p0 += __shfl_down_sync(0xffffffffu, p0, o);
        p1 += __shfl_down_sync(0xffffffffu, p1, o);
    }
    if (lane == 0) {
        s_p[w][0] = p0; s_p[w][1] = p1;
        g_cnt[r] = min(base, CAP);
    }
    __syncthreads();

    // ---- Phase B: GIN0 MLP for 16 rows (2 -> 64 relu -> 64 relu) ----
    const int h = tid & 63;
    const int slot = tid >> 6;
    #pragma unroll
    for (int t = 0; t < 2; t++) {
        const int rr = slot + t * 8;
        const float z = s_b1[h] + s_p[rr][0] * s_w1[h] + s_p[rr][1] * s_w1[HID + h];
        s_z[rr][h] = fmaxf(z, 0.f);
    }
    __syncthreads();
    #pragma unroll
    for (int t = 0; t < 2; t++) {
        const int rr = slot + t * 8;
        float acc = s_b2[h];
        #pragma unroll
        for (int k = 0; k < HID; k++) acc += s_z[rr][k] * s_w2[k * HID + h];
        g_h1[(size_t)(blockIdx.x * 16 + rr) * HID + h] = fmaxf(acc, 0.f);
    }
}

// ============================================================================
// Kernel 2: 32 nodes / 256-thread block (1024 blocks).
//   Phase A: warp-per-node gather (lane = float2 of features, neighbor idx
//            broadcast via shfl, 4 gathers in flight).
//   Phase B/C: GIN1 MLP, thread = (node, 8 outputs), float4 weight loads.
//   s_pool is reused as the z buffer (reg-staged overwrite) to fit 48KB smem.
// ============================================================================
#define K2N 32
__global__ __launch_bounds__(256) void k2_spmm(
    const float* __restrict__ w1, const float* __restrict__ b1,
    const float* __restrict__ w2, const float* __restrict__ b2,
    const float* __restrict__ gp)
{
    __shared__ __align__(16) float s_w1[HID * HID];   // 16 KB
    __shared__ __align__(16) float s_w2[HID * HID];   // 16 KB
    __shared__ __align__(16) float s_b1[HID], s_b2[HID];
    __shared__ __align__(16) float s_pool[K2N][HID];  // 8 KB (pool, then z)
    __shared__ float s_acc[HID];

    const int tid = threadIdx.x;
    for (int i = tid; i < HID * HID; i += 256) { s_w1[i] = w1[i]; s_w2[i] = w2[i]; }
    if (tid < HID) { s_b1[tid] = b1[tid]; s_b2[tid] = b2[tid]; s_acc[tid] = 0.f; }

    const int wid = tid >> 5, lane = tid & 31;
    const int base = blockIdx.x * K2N;
    const int b = base >> 12;
    const float2* __restrict__ h1v = (const float2*)g_h1 + ((size_t)b << 12) * 32;

    // ---- Phase A: gather. 8 warps x 4 nodes ----
    #pragma unroll 1
    for (int t = 0; t < 4; t++) {
        const int ln = wid * 4 + t;
        const int r = base + ln;
        const int cnt = g_cnt[r];
        const int* __restrict__ ip = g_idx + (size_t)r * CAP;
        float px = 0.f, py = 0.f;
        for (int k0 = 0; k0 < cnt; k0 += 32) {
            const int rem = min(cnt - k0, 32);
            const int myenc = (lane < rem) ? ip[k0 + lane] : 0;
            int n = 0;
            for (; n + 4 <= rem; n += 4) {
                const int e0 = __shfl_sync(0xffffffffu, myenc, n);
                const int e1 = __shfl_sync(0xffffffffu, myenc, n + 1);
                const int e2 = __shfl_sync(0xffffffffu, myenc, n + 2);
                const int e3 = __shfl_sync(0xffffffffu, myenc, n + 3);
                const float2 v0 = h1v[(size_t)(e0 & 0x7fffffff) * 32 + lane];
                const float2 v1 = h1v[(size_t)(e1 & 0x7fffffff) * 32 + lane];
                const float2 v2 = h1v[(size_t)(e2 & 0x7fffffff) * 32 + lane];
                const float2 v3 = h1v[(size_t)(e3 & 0x7fffffff) * 32 + lane];
                const float s0 = (e0 < 0) ? 2.f : 1.f, s1 = (e1 < 0) ? 2.f : 1.f;
                const float s2 = (e2 < 0) ? 2.f : 1.f, s3 = (e3 < 0) ? 2.f : 1.f;
                px += s0 * v0.x + s1 * v1.x + s2 * v2.x + s3 * v3.x;
                py += s0 * v0.y + s1 * v1.y + s2 * v2.y + s3 * v3.y;
            }
            for (; n < rem; n++) {
                const int e = __shfl_sync(0xffffffffu, myenc, n);
                const float2 v = h1v[(size_t)(e & 0x7fffffff) * 32 + lane];
                const float s = (e < 0) ? 2.f : 1.f;
                px += s * v.x; py += s * v.y;
            }
        }
        s_pool[ln][2 * lane] = px; s_pool[ln][2 * lane + 1] = py;
    }
    __syncthreads();

    // ---- Phase B: z = relu(pool @ w1 + b1). thread = (node, 8 h) ----
    const int ln2 = tid >> 3;           // 0..31
    const int h0  = (tid & 7) * 8;      // 0,8,..,56
    float4 aA, aB;
    {
        aA = *(const float4*)&s_b1[h0];
        aB = *(const float4*)&s_b1[h0 + 4];
        #pragma unroll 8
        for (int f = 0; f < HID; f++) {
            const float x = s_pool[ln2][f];
            const float4 wA = *(const float4*)&s_w1[f * HID + h0];
            const float4 wB = *(const float4*)&s_w1[f * HID + h0 + 4];
            aA.x += x * wA.x; aA.y += x * wA.y; aA.z += x * wA.z; aA.w += x * wA.w;
            aB.x += x * wB.x; aB.y += x * wB.y; aB.z += x * wB.z; aB.w += x * wB.w;
        }
        aA.x = fmaxf(aA.x, 0.f); aA.y = fmaxf(aA.y, 0.f);
        aA.z = fmaxf(aA.z, 0.f); aA.w = fmaxf(aA.w, 0.f);
        aB.x = fmaxf(aB.x, 0.f); aB.y = fmaxf(aB.y, 0.f);
        aB.z = fmaxf(aB.z, 0.f); aB.w = fmaxf(aB.w, 0.f);
    }
    __syncthreads();                     // all reads of pool done
    *(float4*)&s_pool[ln2][h0]     = aA; // reuse s_pool as z
    *(float4*)&s_pool[ln2][h0 + 4] = aB;
    __syncthreads();

    // ---- Phase C: h2 = relu(z @ w2 + b2), + pooling contribution ----
    {
        aA = *(const float4*)&s_b2[h0];
        aB = *(const float4*)&s_b2[h0 + 4];
        #pragma unroll 8
        for (int f = 0; f < HID; f++) {
            const float x = s_pool[ln2][f];
            const float4 wA = *(const float4*)&s_w2[f * HID + h0];
            const float4 wB = *(const float4*)&s_w2[f * HID + h0 + 4];
            aA.x += x * wA.x; aA.y += x * wA.y; aA.z += x * wA.z; aA.w += x * wA.w;
            aB.x += x * wB.x; aB.y += x * wB.y; aB.z += x * wB.z; aB.w += x * wB.w;
        }
        aA.x = fmaxf(aA.x, 0.f); aA.y = fmaxf(aA.y, 0.f);
        aA.z = fmaxf(aA.z, 0.f); aA.w = fmaxf(aA.w, 0.f);
        aB.x = fmaxf(aB.x, 0.f); aB.y = fmaxf(aB.y, 0.f);
        aB.z = fmaxf(aB.z, 0.f); aB.w = fmaxf(aB.w, 0.f);
        float* orow = g_h2 + (size_t)(base + ln2) * HID;
        *(float4*)&orow[h0]     = aA;
        *(float4*)&orow[h0 + 4] = aB;

        // pooling: gval * h2, reduce over the 4 nodes sharing this warp
        const float gval = gp[base + ln2];
        float v[8] = { gval * aA.x, gval * aA.y, gval * aA.z, gval * aA.w,
                       gval * aB.x, gval * aB.y, gval * aB.z, gval * aB.w };
        #pragma unroll
        for (int i = 0; i < 8; i++) {
            v[i] += __shfl_xor_sync(0xffffffffu, v[i], 8);
            v[i] += __shfl_xor_sync(0xffffffffu, v[i], 16);
        }
        if (lane < 8) {
            #pragma unroll
            for (int i = 0; i < 8; i++)
                atomicAdd(&s_acc[lane * 8 + i], v[i]);
        }
    }
    __syncthreads();
    if (tid < HID) atomicAdd(&g_gge[b * HID + tid], s_acc[tid]);
}

// ============================================================================
// Kernel 3: actor MLP, one warp per (batch, job); last block per batch also
// runs the masked softmax (fence + counter pattern). 256 blocks x 128 thr.
// ============================================================================
__global__ __launch_bounds__(128) void k3_actor(
    const int* __restrict__ cand, const int* __restrict__ mask,
    const float* __restrict__ pmi,
    const float* __restrict__ w1, const float* __restrict__ b1,
    const float* __restrict__ w2, const float* __restrict__ b2,
    const float* __restrict__ w3, const float* __restrict__ b3,
    float* __restrict__ out)
{
    __shared__ float s_x[4][3 * HID];
    __shared__ float s_t[4][HID];
    __shared__ float s_red[JJ];
    __shared__ int   s_ticket;

    const int w    = threadIdx.x >> 5;
    const int lane = threadIdx.x & 31;
    const int job  = blockIdx.x * 4 + w;
    const int bb   = job >> 7;
    const int j    = job & 127;

    const int c = cand[bb * JJ + j];
    const float2* e2 = (const float2*)(g_h2 + ((size_t)bb * NN + c) * HID);
    const float2* g2 = (const float2*)(g_gge + bb * HID);
    const float2* p2 = (const float2*)pmi;
    float2 t;
    t = e2[lane]; s_x[w][2 * lane] = t.x; s_x[w][2 * lane + 1] = t.y;
    t = g2[lane]; s_x[w][HID + 2 * lane] = t.x; s_x[w][HID + 2 * lane + 1] = t.y;
    t = p2[lane]; s_x[w][2 * HID + 2 * lane] = t.x; s_x[w][2 * HID + 2 * lane + 1] = t.y;
    __syncwarp();

    float a0 = b1[lane], a1 = b1[lane + 32];
    #pragma unroll 8
    for (int f = 0; f < 3 * HID; f++) {
        const float xv = s_x[w][f];
        a0 += xv * w1[f * HID + lane];
        a1 += xv * w1[f * HID + lane + 32];
    }
    s_t[w][lane] = tanhf(a0); s_t[w][lane + 32] = tanhf(a1);
    __syncwarp();

    float c0 = b2[lane], c1 = b2[lane + 32];
    #pragma unroll 8
    for (int k = 0; k < HID; k++) {
        const float xv = s_t[w][k];
        c0 += xv * w2[k * HID + lane];
        c1 += xv * w2[k * HID + lane + 32];
    }

    float part = tanhf(c0) * w3[lane] + tanhf(c1) * w3[lane + 32];
    #pragma unroll
    for (int o = 16; o > 0; o >>= 1)
        part += __shfl_down_sync(0xffffffffu, part, o);
    if (lane == 0) {
        float score = (part + b3[0]) * 10.0f;
        if (mask[bb * JJ + j]) score = -INFINITY;
        g_scores[job] = score;
        __threadfence();
    }
    __syncthreads();
    if (threadIdx.x == 0)
        s_ticket = atomicAdd(&g_done[bb], 1);
    __syncthreads();

    if (s_ticket == 31) {
        __threadfence();
        const int jj = threadIdx.x;
        const float sc = __ldcg(&g_scores[bb * JJ + jj]);
        s_red[jj] = sc; __syncthreads();
        for (int s = JJ / 2; s > 0; s >>= 1) {
            if (jj < s) s_red[jj] = fmaxf(s_red[jj], s_red[jj + s]);
            __syncthreads();
        }
        const float mx = s_red[0]; __syncthreads();
        const float e = expf(sc - mx);
        s_red[jj] = e; __syncthreads();
        for (int s = JJ / 2; s > 0; s >>= 1) {
            if (jj < s) s_red[jj] += s_red[jj + s];
            __syncthreads();
        }
        out[bb * JJ + jj] = e / s_red[0];
    }
}

// ============================================================================
extern "C" void kernel_launch(void* const* d_in, const int* in_sizes, int n_in,
                              void* d_out, int out_size)
{
    const float* features   = (const float*)d_in[0];
    const float* graph_pool = (const float*)d_in[1];
    const float* adj        = (const float*)d_in[2];
    const int*   candidate  = (const int*)d_in[3];
    const int*   mask       = (const int*)d_in[4];
    const float* g0w1 = (const float*)d_in[5];
    const float* g0b1 = (const float*)d_in[6];
    const float* g0w2 = (const float*)d_in[7];
    const float* g0b2 = (const float*)d_in[8];
    const float* g1w1 = (const float*)d_in[9];
    const float* g1b1 = (const float*)d_in[10];
    const float* g1w2 = (const float*)d_in[11];
    const float* g1b2 = (const float*)d_in[12];
    const float* pmi  = (const float*)d_in[13];
    const float* aw1  = (const float*)d_in[14];
    const float* ab1  = (const float*)d_in[15];
    const float* aw2  = (const float*)d_in[16];
    const float* ab2  = (const float*)d_in[17];
    const float* aw3  = (const float*)d_in[18];
    const float* ab3  = (const float*)d_in[19];
    float* out = (float*)d_out;

    k1_scan<<<NROWS / 16, 512>>>(adj, features, g0w1, g0b1, g0w2, g0b2);
    k2_spmm<<<NROWS / K2N, 256>>>(g1w1, g1b1, g1w2, g1b2, graph_pool);
    k3_actor<<<BB * JJ / 4, 128>>>(candidate, mask, pmi,
                                   aw1, ab1, aw2, ab2, aw3, ab3, out);
}

// round 6
// speedup vs baseline: 1.1397x; 1.1397x over previous
#include <cuda_runtime.h>
#include <cstdint>
#include <math.h>

#define BB   8
#define NN   4096
#define HID  64
#define JJ   128
#define CAP  96
#define NROWS (BB*NN)   // 32768

// ---- scratch (device globals; no allocation allowed) ----
__device__ int   g_cnt[NROWS];
__device__ int   g_idx[(size_t)NROWS * CAP];   // packed: col | (val==2 ? 0x80000000 : 0)
__device__ float g_h1[(size_t)NROWS * HID];    // 8 MB
__device__ float g_h2[(size_t)NROWS * HID];    // 8 MB
__device__ float g_gge[BB * HID];              // global graph embedding accumulator
__device__ float g_scores[BB * JJ];            // actor scores before softmax
__device__ int   g_done[BB];                   // per-batch completion counters

// ============================================================================
// Kernel 1: stream adj once. Warp-per-row, group-skip nonzero detection,
// per-warp shared-atomic compaction (no ballots, no popc chains).
// 16 rows / 512-thread block + fused GIN0 MLP (2->64->64).
// ============================================================================
__global__ __launch_bounds__(512) void k1_scan(
    const float* __restrict__ adj, const float* __restrict__ feat,
    const float* __restrict__ w1, const float* __restrict__ b1,
    const float* __restrict__ w2, const float* __restrict__ b2)
{
    __shared__ float s_w2[HID * HID];   // 16 KB
    __shared__ float s_w1[2 * HID];
    __shared__ float s_b1[HID], s_b2[HID];
    __shared__ float s_p[16][2];
    __shared__ float s_z[16][HID];
    __shared__ int   s_cnt[16];

    const int tid  = threadIdx.x;
    const int w    = tid >> 5;
    const int lane = tid & 31;

    for (int i = tid; i < HID * HID; i += 512) s_w2[i] = w2[i];
    if (tid < 2 * HID) s_w1[tid] = w1[tid];
    if (tid < HID) { s_b1[tid] = b1[tid]; s_b2[tid] = b2[tid]; }
    if (lane == 0) s_cnt[w] = 0;
    if (blockIdx.x == 0) {              // zero accumulators for k2/k3
        if (tid < BB * HID) g_gge[tid] = 0.f;
        if (tid < BB) g_done[tid] = 0;
    }
    __syncwarp();                        // s_cnt[w] visible to this warp

    // ---- Phase A: each warp scans one full adjacency row ----
    const int r = blockIdx.x * 16 + w;
    const int b = r >> 12;
    const uint4* __restrict__ arow = (const uint4*)(adj + (size_t)r * NN);  // 1024
    const float2* __restrict__ f2p = (const float2*)feat + (size_t)b * NN;
    int* __restrict__ irow = g_idx + (size_t)r * CAP;

    float p0 = 0.f, p1 = 0.f;

#define PROC_ELEM(bits, jj) do {                                           \
        if ((bits) != 0u) {                                                \
            const int pos = atomicAdd(&s_cnt[w], 1);                       \
            const bool two = ((bits) == 0x40000000u);                      \
            if (pos < CAP) irow[pos] = (jj) | (two ? 0x80000000 : 0);      \
            const float2 f = f2p[(jj)];                                    \
            const float sv = two ? 2.f : 1.f;                              \
            p0 += sv * f.x; p1 += sv * f.y;                                \
        }                                                                  \
    } while (0)

    #pragma unroll 1
    for (int it = 0; it < 8; it++) {
        uint4 v0 = arow[it * 128 + lane];
        uint4 v1 = arow[it * 128 + lane + 32];
        uint4 v2 = arow[it * 128 + lane + 64];
        uint4 v3 = arow[it * 128 + lane + 96];
        #pragma unroll
        for (int k = 0; k < 4; k++) {
            const uint4 v = (k == 0) ? v0 : (k == 1) ? v1 : (k == 2) ? v2 : v3;
            if (v.x | v.y | v.z | v.w) {      // per-lane, rare (~2% of groups)
                const int jb = (it * 128 + lane + 32 * k) * 4;
                PROC_ELEM(v.x, jb + 0);
                PROC_ELEM(v.y, jb + 1);
                PROC_ELEM(v.z, jb + 2);
                PROC_ELEM(v.w, jb + 3);
            }
        }
    }
#undef PROC_ELEM

    // warp-reduce pooled features
    #pragma unroll
    for (int o = 16; o > 0; o >>= 1) {
        p0 += __shfl_down_sync(0xffffffffu, p0, o);
        p1 += __shfl_down_sync(0xffffffffu, p1, o);
    }
    __syncwarp();
    if (lane == 0) {
        s_p[w][0] = p0; s_p[w][1] = p1;
        g_cnt[r] = min(s_cnt[w], CAP);
    }
    __syncthreads();

    // ---- Phase B: GIN0 MLP for 16 rows (2 -> 64 relu -> 64 relu) ----
    const int h = tid & 63;
    const int slot = tid >> 6;
    #pragma unroll
    for (int t = 0; t < 2; t++) {
        const int rr = slot + t * 8;
        const float z = s_b1[h] + s_p[rr][0] * s_w1[h] + s_p[rr][1] * s_w1[HID + h];
        s_z[rr][h] = fmaxf(z, 0.f);
    }
    __syncthreads();
    #pragma unroll
    for (int t = 0; t < 2; t++) {
        const int rr = slot + t * 8;
        float acc = s_b2[h];
        #pragma unroll
        for (int k = 0; k < HID; k++) acc += s_z[rr][k] * s_w2[k * HID + h];
        g_h1[(size_t)(blockIdx.x * 16 + rr) * HID + h] = fmaxf(acc, 0.f);
    }
}

// ============================================================================
// Kernel 2: 16 nodes / 256-thread block (2048 blocks).
//   Phase A: warp-per-node gather (lane = float2, 8 neighbors in flight,
//            only 2 nodes serial per warp).
//   Phase B/C: GIN1 MLP, thread = (node, 4 outputs), float4 weight loads.
//   s_pool reused as z. smem ~37 KB.
// ============================================================================
#define K2N 16
__global__ __launch_bounds__(256) void k2_spmm(
    const float* __restrict__ w1, const float* __restrict__ b1,
    const float* __restrict__ w2, const float* __restrict__ b2,
    const float* __restrict__ gp)
{
    __shared__ __align__(16) float s_w1[HID * HID];   // 16 KB
    __shared__ __align__(16) float s_w2[HID * HID];   // 16 KB
    __shared__ __align__(16) float s_b1[HID], s_b2[HID];
    __shared__ __align__(16) float s_pool[K2N][HID];  // 4 KB (pool, then z)
    __shared__ float s_acc[HID];

    const int tid = threadIdx.x;
    for (int i = tid; i < HID * HID; i += 256) { s_w1[i] = w1[i]; s_w2[i] = w2[i]; }
    if (tid < HID) { s_b1[tid] = b1[tid]; s_b2[tid] = b2[tid]; s_acc[tid] = 0.f; }

    const int wid = tid >> 5, lane = tid & 31;
    const int base = blockIdx.x * K2N;
    const int b = base >> 12;
    const float2* __restrict__ h1v = (const float2*)g_h1 + ((size_t)b << 12) * 32;

    // ---- Phase A: gather. 8 warps x 2 nodes, 8 gathers in flight ----
    #pragma unroll 1
    for (int t = 0; t < 2; t++) {
        const int ln = wid * 2 + t;
        const int r = base + ln;
        const int cnt = g_cnt[r];
        const int* __restrict__ ip = g_idx + (size_t)r * CAP;
        float px = 0.f, py = 0.f;
        for (int k0 = 0; k0 < cnt; k0 += 32) {
            const int rem = min(cnt - k0, 32);
            const int myenc = (lane < rem) ? ip[k0 + lane] : 0;
            int n = 0;
            for (; n + 8 <= rem; n += 8) {
                int e[8];
                #pragma unroll
                for (int q = 0; q < 8; q++)
                    e[q] = __shfl_sync(0xffffffffu, myenc, n + q);
                float2 v[8];
                #pragma unroll
                for (int q = 0; q < 8; q++)
                    v[q] = h1v[(size_t)(e[q] & 0x7fffffff) * 32 + lane];
                #pragma unroll
                for (int q = 0; q < 8; q++) {
                    const float s = (e[q] < 0) ? 2.f : 1.f;
                    px += s * v[q].x; py += s * v[q].y;
                }
            }
            for (; n + 4 <= rem; n += 4) {
                int e[4];
                #pragma unroll
                for (int q = 0; q < 4; q++)
                    e[q] = __shfl_sync(0xffffffffu, myenc, n + q);
                float2 v[4];
                #pragma unroll
                for (int q = 0; q < 4; q++)
                    v[q] = h1v[(size_t)(e[q] & 0x7fffffff) * 32 + lane];
                #pragma unroll
                for (int q = 0; q < 4; q++) {
                    const float s = (e[q] < 0) ? 2.f : 1.f;
                    px += s * v[q].x; py += s * v[q].y;
                }
            }
            for (; n < rem; n++) {
                const int e = __shfl_sync(0xffffffffu, myenc, n);
                const float2 v = h1v[(size_t)(e & 0x7fffffff) * 32 + lane];
                const float s = (e < 0) ? 2.f : 1.f;
                px += s * v.x; py += s * v.y;
            }
        }
        s_pool[ln][2 * lane] = px; s_pool[ln][2 * lane + 1] = py;
    }
    __syncthreads();

    // ---- Phase B: z = relu(pool @ w1 + b1). thread = (node, 4 h) ----
    const int ln2 = tid >> 4;           // 0..15
    const int h0  = (tid & 15) * 4;     // 0,4,..,60
    float4 acc;
    {
        acc = *(const float4*)&s_b1[h0];
        #pragma unroll 8
        for (int f = 0; f < HID; f++) {
            const float x = s_pool[ln2][f];
            const float4 w4 = *(const float4*)&s_w1[f * HID + h0];
            acc.x += x * w4.x; acc.y += x * w4.y;
            acc.z += x * w4.z; acc.w += x * w4.w;
        }
        acc.x = fmaxf(acc.x, 0.f); acc.y = fmaxf(acc.y, 0.f);
        acc.z = fmaxf(acc.z, 0.f); acc.w = fmaxf(acc.w, 0.f);
    }
    __syncthreads();                     // all reads of pool done
    *(float4*)&s_pool[ln2][h0] = acc;    // reuse s_pool as z
    __syncthreads();

    // ---- Phase C: h2 = relu(z @ w2 + b2), + pooling contribution ----
    {
        acc = *(const float4*)&s_b2[h0];
        #pragma unroll 8
        for (int f = 0; f < HID; f++) {
            const float x = s_pool[ln2][f];
            const float4 w4 = *(const float4*)&s_w2[f * HID + h0];
            acc.x += x * w4.x; acc.y += x * w4.y;
            acc.z += x * w4.z; acc.w += x * w4.w;
        }
        acc.x = fmaxf(acc.x, 0.f); acc.y = fmaxf(acc.y, 0.f);
        acc.z = fmaxf(acc.z, 0.f); acc.w = fmaxf(acc.w, 0.f);
        *(float4*)&(g_h2 + (size_t)(base + ln2) * HID)[h0] = acc;

        // pooling: gval * h2; lanes 0-15 = node A, 16-31 = node B
        const float gval = gp[base + ln2];
        float v[4] = { gval * acc.x, gval * acc.y, gval * acc.z, gval * acc.w };
        #pragma unroll
        for (int i = 0; i < 4; i++)
            v[i] += __shfl_xor_sync(0xffffffffu, v[i], 16);
        if (lane < 16) {
            #pragma unroll
            for (int i = 0; i < 4; i++)
                atomicAdd(&s_acc[h0 + i], v[i]);
        }
    }
    __syncthreads();
    if (tid < HID) atomicAdd(&g_gge[b * HID + tid], s_acc[tid]);
}

// ============================================================================
// Kernel 3: actor MLP, one warp per (batch, job); last block per batch also
// runs the masked softmax (fence + counter pattern). 256 blocks x 128 thr.
// ============================================================================
__global__ __launch_bounds__(128) void k3_actor(
    const int* __restrict__ cand, const int* __restrict__ mask,
    const float* __restrict__ pmi,
    const float* __restrict__ w1, const float* __restrict__ b1,
    const float* __restrict__ w2, const float* __restrict__ b2,
    const float* __restrict__ w3, const float* __restrict__ b3,
    float* __restrict__ out)
{
    __shared__ float s_x[4][3 * HID];
    __shared__ float s_t[4][HID];
    __shared__ float s_red[JJ];
    __shared__ int   s_ticket;

    const int w    = threadIdx.x >> 5;
    const int lane = threadIdx.x & 31;
    const int job  = blockIdx.x * 4 + w;
    const int bb   = job >> 7;
    const int j    = job & 127;

    const int c = cand[bb * JJ + j];
    const float2* e2 = (const float2*)(g_h2 + ((size_t)bb * NN + c) * HID);
    const float2* g2 = (const float2*)(g_gge + bb * HID);
    const float2* p2 = (const float2*)pmi;
    float2 t;
    t = e2[lane]; s_x[w][2 * lane] = t.x; s_x[w][2 * lane + 1] = t.y;
    t = g2[lane]; s_x[w][HID + 2 * lane] = t.x; s_x[w][HID + 2 * lane + 1] = t.y;
    t = p2[lane]; s_x[w][2 * HID + 2 * lane] = t.x; s_x[w][2 * HID + 2 * lane + 1] = t.y;
    __syncwarp();

    float a0 = b1[lane], a1 = b1[lane + 32];
    #pragma unroll 8
    for (int f = 0; f < 3 * HID; f++) {
        const float xv = s_x[w][f];
        a0 += xv * w1[f * HID + lane];
        a1 += xv * w1[f * HID + lane + 32];
    }
    s_t[w][lane] = tanhf(a0); s_t[w][lane + 32] = tanhf(a1);
    __syncwarp();

    float c0 = b2[lane], c1 = b2[lane + 32];
    #pragma unroll 8
    for (int k = 0; k < HID; k++) {
        const float xv = s_t[w][k];
        c0 += xv * w2[k * HID + lane];
        c1 += xv * w2[k * HID + lane + 32];
    }

    float part = tanhf(c0) * w3[lane] + tanhf(c1) * w3[lane + 32];
    #pragma unroll
    for (int o = 16; o > 0; o >>= 1)
        part += __shfl_down_sync(0xffffffffu, part, o);
    if (lane == 0) {
        float score = (part + b3[0]) * 10.0f;
        if (mask[bb * JJ + j]) score = -INFINITY;
        g_scores[job] = score;
        __threadfence();
    }
    __syncthreads();
    if (threadIdx.x == 0)
        s_ticket = atomicAdd(&g_done[bb], 1);
    __syncthreads();

    if (s_ticket == 31) {
        __threadfence();
        const int jj = threadIdx.x;
        const float sc = __ldcg(&g_scores[bb * JJ + jj]);
        s_red[jj] = sc; __syncthreads();
        for (int s = JJ / 2; s > 0; s >>= 1) {
            if (jj < s) s_red[jj] = fmaxf(s_red[jj], s_red[jj + s]);
            __syncthreads();
        }
        const float mx = s_red[0]; __syncthreads();
        const float e = expf(sc - mx);
        s_red[jj] = e; __syncthreads();
        for (int s = JJ / 2; s > 0; s >>= 1) {
            if (jj < s) s_red[jj] += s_red[jj + s];
            __syncthreads();
        }
        out[bb * JJ + jj] = e / s_red[0];
    }
}

// ============================================================================
extern "C" void kernel_launch(void* const* d_in, const int* in_sizes, int n_in,
                              void* d_out, int out_size)
{
    const float* features   = (const float*)d_in[0];
    const float* graph_pool = (const float*)d_in[1];
    const float* adj        = (const float*)d_in[2];
    const int*   candidate  = (const int*)d_in[3];
    const int*   mask       = (const int*)d_in[4];
    const float* g0w1 = (const float*)d_in[5];
    const float* g0b1 = (const float*)d_in[6];
    const float* g0w2 = (const float*)d_in[7];
    const float* g0b2 = (const float*)d_in[8];
    const float* g1w1 = (const float*)d_in[9];
    const float* g1b1 = (const float*)d_in[10];
    const float* g1w2 = (const float*)d_in[11];
    const float* g1b2 = (const float*)d_in[12];
    const float* pmi  = (const float*)d_in[13];
    const float* aw1  = (const float*)d_in[14];
    const float* ab1  = (const float*)d_in[15];
    const float* aw2  = (const float*)d_in[16];
    const float* ab2  = (const float*)d_in[17];
    const float* aw3  = (const float*)d_in[18];
    const float* ab3  = (const float*)d_in[19];
    float* out = (float*)d_out;

    k1_scan<<<NROWS / 16, 512>>>(adj, features, g0w1, g0b1, g0w2, g0b2);
    k2_spmm<<<NROWS / K2N, 256>>>(g1w1, g1b1, g1w2, g1b2, graph_pool);
    k3_actor<<<BB * JJ / 4, 128>>>(candidate, mask, pmi,
                                   aw1, ab1, aw2, ab2, aw3, ab3, out);
}

// round 7
// speedup vs baseline: 1.1845x; 1.0393x over previous
#include <cuda_runtime.h>
#include <cstdint>
#include <math.h>

#define BB   8
#define NN   4096
#define HID  64
#define JJ   128
#define CAP  96
#define NROWS (BB*NN)   // 32768

// ---- scratch (device globals; no allocation allowed) ----
__device__ int   g_cnt[NROWS];
__device__ int   g_idx[(size_t)NROWS * CAP];   // packed: col | (val==2 ? 0x80000000 : 0)
__device__ float g_h1[(size_t)NROWS * HID];    // 8 MB
__device__ float g_h2[(size_t)NROWS * HID];    // 8 MB
__device__ float g_gge[BB * HID];              // global graph embedding accumulator
__device__ float g_scores[BB * JJ];            // actor scores before softmax
__device__ int   g_done[BB];                   // per-batch completion counters

__device__ __forceinline__ void cp_async16(void* smem_dst, const void* gmem_src) {
    unsigned sa = (unsigned)__cvta_generic_to_shared(smem_dst);
    asm volatile("cp.async.cg.shared.global [%0], [%1], 16;\n"
                 :: "r"(sa), "l"(gmem_src));
}
__device__ __forceinline__ void cp_commit() {
    asm volatile("cp.async.commit_group;\n");
}
template <int N>
__device__ __forceinline__ void cp_wait() {
    asm volatile("cp.async.wait_group %0;\n" :: "n"(N));
}

// ============================================================================
// Kernel 1: stream adj once via per-warp cp.async ring (3 buffers x 512 B,
// 2 chunks in flight). Warp-per-row, group-skip, shared-atomic compaction.
// 16 rows / 512-thread block + fused GIN0 MLP (2->64->64).
// ============================================================================
#define NBUF 3
#define NCHUNK 32   // 4096 floats / 128 per chunk
__global__ __launch_bounds__(512) void k1_scan(
    const float* __restrict__ adj, const float* __restrict__ feat,
    const float* __restrict__ w1, const float* __restrict__ b1,
    const float* __restrict__ w2, const float* __restrict__ b2)
{
    __shared__ float s_w2[HID * HID];            // 16 KB
    __shared__ uint4 s_buf[16][NBUF][32];        // 24 KB streaming ring
    __shared__ float s_w1[2 * HID];
    __shared__ float s_b1[HID], s_b2[HID];
    __shared__ float s_p[16][2];
    __shared__ float s_z[16][HID];
    __shared__ int   s_cnt[16];

    const int tid  = threadIdx.x;
    const int w    = tid >> 5;
    const int lane = tid & 31;

    for (int i = tid; i < HID * HID; i += 512) s_w2[i] = w2[i];
    if (tid < 2 * HID) s_w1[tid] = w1[tid];
    if (tid < HID) { s_b1[tid] = b1[tid]; s_b2[tid] = b2[tid]; }
    if (lane == 0) s_cnt[w] = 0;
    if (blockIdx.x == 0) {              // zero accumulators for k2/k3
        if (tid < BB * HID) g_gge[tid] = 0.f;
        if (tid < BB) g_done[tid] = 0;
    }
    __syncwarp();                        // s_cnt[w] visible within warp

    // ---- Phase A: stream one adjacency row per warp ----
    const int r = blockIdx.x * 16 + w;
    const int b = r >> 12;
    const float* __restrict__ grow = adj + (size_t)r * NN;
    const float2* __restrict__ f2p = (const float2*)feat + (size_t)b * NN;
    int* __restrict__ irow = g_idx + (size_t)r * CAP;

    float p0 = 0.f, p1 = 0.f;

#define PROC_ELEM(bits, jj) do {                                           \
        if ((bits) != 0u) {                                                \
            const int pos = atomicAdd(&s_cnt[w], 1);                       \
            const bool two = ((bits) == 0x40000000u);                      \
            if (pos < CAP) irow[pos] = (jj) | (two ? 0x80000000 : 0);      \
            const float2 f = f2p[(jj)];                                    \
            const float sv = two ? 2.f : 1.f;                              \
            p0 += sv * f.x; p1 += sv * f.y;                                \
        }                                                                  \
    } while (0)

#define PROC_CHUNK(c) do {                                                 \
        const uint4 v = s_buf[w][(c) % NBUF][lane];                        \
        if (v.x | v.y | v.z | v.w) {                                       \
            const int jb = (c) * 128 + lane * 4;                           \
            PROC_ELEM(v.x, jb + 0);                                        \
            PROC_ELEM(v.y, jb + 1);                                        \
            PROC_ELEM(v.z, jb + 2);                                        \
            PROC_ELEM(v.w, jb + 3);                                        \
        }                                                                  \
    } while (0)

    // prologue: issue chunks 0..2
    #pragma unroll
    for (int c = 0; c < NBUF; c++) {
        cp_async16(&s_buf[w][c][lane], grow + c * 128 + lane * 4);
        cp_commit();
    }
    // main loop: process c, keep 2 ahead in flight
    #pragma unroll 1
    for (int c = 0; c < NCHUNK - NBUF; c++) {
        cp_wait<NBUF - 1>();             // chunk c landed
        PROC_CHUNK(c);
        cp_async16(&s_buf[w][(c + NBUF) % NBUF][lane],
                   grow + (c + NBUF) * 128 + lane * 4);
        cp_commit();
    }
    cp_wait<0>();
    #pragma unroll
    for (int c = NCHUNK - NBUF; c < NCHUNK; c++) PROC_CHUNK(c);
#undef PROC_CHUNK
#undef PROC_ELEM

    // warp-reduce pooled features
    #pragma unroll
    for (int o = 16; o > 0; o >>= 1) {
        p0 += __shfl_down_sync(0xffffffffu, p0, o);
        p1 += __shfl_down_sync(0xffffffffu, p1, o);
    }
    __syncwarp();
    if (lane == 0) {
        s_p[w][0] = p0; s_p[w][1] = p1;
        g_cnt[r] = min(s_cnt[w], CAP);
    }
    __syncthreads();

    // ---- Phase B: GIN0 MLP for 16 rows (2 -> 64 relu -> 64 relu) ----
    const int h = tid & 63;
    const int slot = tid >> 6;
    #pragma unroll
    for (int t = 0; t < 2; t++) {
        const int rr = slot + t * 8;
        const float z = s_b1[h] + s_p[rr][0] * s_w1[h] + s_p[rr][1] * s_w1[HID + h];
        s_z[rr][h] = fmaxf(z, 0.f);
    }
    __syncthreads();
    #pragma unroll
    for (int t = 0; t < 2; t++) {
        const int rr = slot + t * 8;
        float acc = s_b2[h];
        #pragma unroll
        for (int k = 0; k < HID; k++) acc += s_z[rr][k] * s_w2[k * HID + h];
        g_h1[(size_t)(blockIdx.x * 16 + rr) * HID + h] = fmaxf(acc, 0.f);
    }
}

// ============================================================================
// Kernel 2: 32 nodes / 256-thread block (1024 blocks).
//   Gather: 8 warps x 4 nodes INTERLEAVED (4 independent loads per step).
//   MLP: thread = (2 nodes, 4 outputs) -> 3 B smem / FMA; w1 and w2 share
//   one 16 KB smem buffer loaded sequentially. s_pool reused as z.
// ============================================================================
#define K2N 32
__global__ __launch_bounds__(256) void k2_spmm(
    const float* __restrict__ w1, const float* __restrict__ b1,
    const float* __restrict__ w2, const float* __restrict__ b2,
    const float* __restrict__ gp)
{
    __shared__ __align__(16) float s_w[HID * HID];     // 16 KB (w1 then w2)
    __shared__ __align__(16) float s_pool[K2N][HID];   // 8 KB (pool, then z)
    __shared__ __align__(16) float s_b1[HID], s_b2[HID];
    __shared__ float s_acc[HID];

    const int tid = threadIdx.x;
    for (int i = tid; i < HID * HID; i += 256) s_w[i] = w1[i];
    if (tid < HID) { s_b1[tid] = b1[tid]; s_b2[tid] = b2[tid]; s_acc[tid] = 0.f; }

    const int wid = tid >> 5, lane = tid & 31;
    const int base = blockIdx.x * K2N;
    const int b = base >> 12;
    const float2* __restrict__ h1v = (const float2*)g_h1 + ((size_t)b << 12) * 32;

    // ---- Phase A: gather. 8 warps x 4 nodes interleaved ----
    {
        const int ln0 = wid * 4;
        int cnt[4]; const int* ip[4];
        #pragma unroll
        for (int i = 0; i < 4; i++) {
            const int rr = base + ln0 + i;
            cnt[i] = g_cnt[rr];
            ip[i]  = g_idx + (size_t)rr * CAP;
        }
        float ax[4] = {0.f, 0.f, 0.f, 0.f}, ay[4] = {0.f, 0.f, 0.f, 0.f};
        const int maxc = max(max(cnt[0], cnt[1]), max(cnt[2], cnt[3]));
        for (int k0 = 0; k0 < maxc; k0 += 32) {
            int enc[4];
            #pragma unroll
            for (int i = 0; i < 4; i++)
                enc[i] = (k0 + lane < cnt[i]) ? ip[i][k0 + lane] : 0;
            const int rem = min(maxc - k0, 32);
            #pragma unroll 2
            for (int n = 0; n < rem; n++) {
                #pragma unroll
                for (int i = 0; i < 4; i++) {
                    const int e = __shfl_sync(0xffffffffu, enc[i], n);
                    if (k0 + n < cnt[i]) {       // warp-uniform predicate
                        const float2 v = h1v[(size_t)(e & 0x7fffffff) * 32 + lane];
                        const float s = (e < 0) ? 2.f : 1.f;
                        ax[i] += s * v.x; ay[i] += s * v.y;
                    }
                }
            }
        }
        #pragma unroll
        for (int i = 0; i < 4; i++) {
            s_pool[ln0 + i][2 * lane]     = ax[i];
            s_pool[ln0 + i][2 * lane + 1] = ay[i];
        }
    }
    __syncthreads();

    // ---- Phase B: z = relu(pool @ w1 + b1). thread = (2 nodes, 4 h) ----
    const int pr = tid >> 4;            // node pair 0..15
    const int h0 = (tid & 15) * 4;      // 0,4,..,60
    const int nA = 2 * pr, nB = 2 * pr + 1;
    float4 aA, aB;
    {
        aA = *(const float4*)&s_b1[h0];
        aB = aA;
        #pragma unroll 8
        for (int f = 0; f < HID; f++) {
            const float xA = s_pool[nA][f];
            const float xB = s_pool[nB][f];
            const float4 w4 = *(const float4*)&s_w[f * HID + h0];
            aA.x += xA * w4.x; aA.y += xA * w4.y; aA.z += xA * w4.z; aA.w += xA * w4.w;
            aB.x += xB * w4.x; aB.y += xB * w4.y; aB.z += xB * w4.z; aB.w += xB * w4.w;
        }
        aA.x = fmaxf(aA.x, 0.f); aA.y = fmaxf(aA.y, 0.f);
        aA.z = fmaxf(aA.z, 0.f); aA.w = fmaxf(aA.w, 0.f);
        aB.x = fmaxf(aB.x, 0.f); aB.y = fmaxf(aB.y, 0.f);
        aB.z = fmaxf(aB.z, 0.f); aB.w = fmaxf(aB.w, 0.f);
    }
    __syncthreads();                     // all pool & w1 reads done
    *(float4*)&s_pool[nA][h0] = aA;      // reuse s_pool as z
    *(float4*)&s_pool[nB][h0] = aB;
    for (int i = tid; i < HID * HID; i += 256) s_w[i] = w2[i];   // overwrite w1
    __syncthreads();

    // ---- Phase C: h2 = relu(z @ w2 + b2), + pooling contribution ----
    {
        aA = *(const float4*)&s_b2[h0];
        aB = aA;
        #pragma unroll 8
        for (int f = 0; f < HID; f++) {
            const float xA = s_pool[nA][f];
            const float xB = s_pool[nB][f];
            const float4 w4 = *(const float4*)&s_w[f * HID + h0];
            aA.x += xA * w4.x; aA.y += xA * w4.y; aA.z += xA * w4.z; aA.w += xA * w4.w;
            aB.x += xB * w4.x; aB.y += xB * w4.y; aB.z += xB * w4.z; aB.w += xB * w4.w;
        }
        aA.x = fmaxf(aA.x, 0.f); aA.y = fmaxf(aA.y, 0.f);
        aA.z = fmaxf(aA.z, 0.f); aA.w = fmaxf(aA.w, 0.f);
        aB.x = fmaxf(aB.x, 0.f); aB.y = fmaxf(aB.y, 0.f);
        aB.z = fmaxf(aB.z, 0.f); aB.w = fmaxf(aB.w, 0.f);
        *(float4*)&(g_h2 + (size_t)(base + nA) * HID)[h0] = aA;
        *(float4*)&(g_h2 + (size_t)(base + nB) * HID)[h0] = aB;

        const float gA = gp[base + nA], gB = gp[base + nB];
        float v0 = gA * aA.x + gB * aB.x;
        float v1 = gA * aA.y + gB * aB.y;
        float v2 = gA * aA.z + gB * aB.z;
        float v3 = gA * aA.w + gB * aB.w;
        // lanes l and l+16 share the same h0 -> combine, halve atomics
        v0 += __shfl_xor_sync(0xffffffffu, v0, 16);
        v1 += __shfl_xor_sync(0xffffffffu, v1, 16);
        v2 += __shfl_xor_sync(0xffffffffu, v2, 16);
        v3 += __shfl_xor_sync(0xffffffffu, v3, 16);
        if (lane < 16) {
            atomicAdd(&s_acc[h0 + 0], v0);
            atomicAdd(&s_acc[h0 + 1], v1);
            atomicAdd(&s_acc[h0 + 2], v2);
            atomicAdd(&s_acc[h0 + 3], v3);
        }
    }
    __syncthreads();
    if (tid < HID) atomicAdd(&g_gge[b * HID + tid], s_acc[tid]);
}

// ============================================================================
// Kernel 3: actor MLP, one warp per (batch, job); last block per batch also
// runs the masked softmax (fence + counter pattern). 256 blocks x 128 thr.
// ============================================================================
__global__ __launch_bounds__(128) void k3_actor(
    const int* __restrict__ cand, const int* __restrict__ mask,
    const float* __restrict__ pmi,
    const float* __restrict__ w1, const float* __restrict__ b1,
    const float* __restrict__ w2, const float* __restrict__ b2,
    const float* __restrict__ w3, const float* __restrict__ b3,
    float* __restrict__ out)
{
    __shared__ float s_x[4][3 * HID];
    __shared__ float s_t[4][HID];
    __shared__ float s_red[JJ];
    __shared__ int   s_ticket;

    const int w    = threadIdx.x >> 5;
    const int lane = threadIdx.x & 31;
    const int job  = blockIdx.x * 4 + w;
    const int bb   = job >> 7;
    const int j    = job & 127;

    const int c = cand[bb * JJ + j];
    const float2* e2 = (const float2*)(g_h2 + ((size_t)bb * NN + c) * HID);
    const float2* g2 = (const float2*)(g_gge + bb * HID);
    const float2* p2 = (const float2*)pmi;
    float2 t;
    t = e2[lane]; s_x[w][2 * lane] = t.x; s_x[w][2 * lane + 1] = t.y;
    t = g2[lane]; s_x[w][HID + 2 * lane] = t.x; s_x[w][HID + 2 * lane + 1] = t.y;
    t = p2[lane]; s_x[w][2 * HID + 2 * lane] = t.x; s_x[w][2 * HID + 2 * lane + 1] = t.y;
    __syncwarp();

    float a0 = b1[lane], a1 = b1[lane + 32];
    #pragma unroll 8
    for (int f = 0; f < 3 * HID; f++) {
        const float xv = s_x[w][f];
        a0 += xv * w1[f * HID + lane];
        a1 += xv * w1[f * HID + lane + 32];
    }
    s_t[w][lane] = tanhf(a0); s_t[w][lane + 32] = tanhf(a1);
    __syncwarp();

    float c0 = b2[lane], c1 = b2[lane + 32];
    #pragma unroll 8
    for (int k = 0; k < HID; k++) {
        const float xv = s_t[w][k];
        c0 += xv * w2[k * HID + lane];
        c1 += xv * w2[k * HID + lane + 32];
    }

    float part = tanhf(c0) * w3[lane] + tanhf(c1) * w3[lane + 32];
    #pragma unroll
    for (int o = 16; o > 0; o >>= 1)
        part += __shfl_down_sync(0xffffffffu, part, o);
    if (lane == 0) {
        float score = (part + b3[0]) * 10.0f;
        if (mask[bb * JJ + j]) score = -INFINITY;
        g_scores[job] = score;
        __threadfence();
    }
    __syncthreads();
    if (threadIdx.x == 0)
        s_ticket = atomicAdd(&g_done[bb], 1);
    __syncthreads();

    if (s_ticket == 31) {
        __threadfence();
        const int jj = threadIdx.x;
        const float sc = __ldcg(&g_scores[bb * JJ + jj]);
        s_red[jj] = sc; __syncthreads();
        for (int s = JJ / 2; s > 0; s >>= 1) {
            if (jj < s) s_red[jj] = fmaxf(s_red[jj], s_red[jj + s]);
            __syncthreads();
        }
        const float mx = s_red[0]; __syncthreads();
        const float e = expf(sc - mx);
        s_red[jj] = e; __syncthreads();
        for (int s = JJ / 2; s > 0; s >>= 1) {
            if (jj < s) s_red[jj] += s_red[jj + s];
            __syncthreads();
        }
        out[bb * JJ + jj] = e / s_red[0];
    }
}

// ============================================================================
extern "C" void kernel_launch(void* const* d_in, const int* in_sizes, int n_in,
                              void* d_out, int out_size)
{
    const float* features   = (const float*)d_in[0];
    const float* graph_pool = (const float*)d_in[1];
    const float* adj        = (const float*)d_in[2];
    const int*   candidate  = (const int*)d_in[3];
    const int*   mask       = (const int*)d_in[4];
    const float* g0w1 = (const float*)d_in[5];
    const float* g0b1 = (const float*)d_in[6];
    const float* g0w2 = (const float*)d_in[7];
    const float* g0b2 = (const float*)d_in[8];
    const float* g1w1 = (const float*)d_in[9];
    const float* g1b1 = (const float*)d_in[10];
    const float* g1w2 = (const float*)d_in[11];
    const float* g1b2 = (const float*)d_in[12];
    const float* pmi  = (const float*)d_in[13];
    const float* aw1  = (const float*)d_in[14];
    const float* ab1  = (const float*)d_in[15];
    const float* aw2  = (const float*)d_in[16];
    const float* ab2  = (const float*)d_in[17];
    const float* aw3  = (const float*)d_in[18];
    const float* ab3  = (const float*)d_in[19];
    float* out = (float*)d_out;

    k1_scan<<<NROWS / 16, 512>>>(adj, features, g0w1, g0b1, g0w2, g0b2);
    k2_spmm<<<NROWS / K2N, 256>>>(g1w1, g1b1, g1w2, g1b2, graph_pool);
    k3_actor<<<BB * JJ / 4, 128>>>(candidate, mask, pmi,
                                   aw1, ab1, aw2, ab2, aw3, ab3, out);
}

// round 8
// speedup vs baseline: 1.1972x; 1.0107x over previous
#include <cuda_runtime.h>
#include <cstdint>
#include <math.h>

#define BB   8
#define NN   4096
#define HID  64
#define JJ   128
#define CAP  96
#define NROWS (BB*NN)   // 32768

// ---- scratch (device globals; no allocation allowed) ----
__device__ int   g_cnt[NROWS];
__device__ int   g_idx[(size_t)NROWS * CAP];   // packed: col | (val==2 ? 0x80000000 : 0)
__device__ float g_h1[(size_t)NROWS * HID];    // 8 MB
__device__ float g_pool[(size_t)NROWS * HID];  // 8 MB (layer-1 neighbor sums)
__device__ float g_h2[(size_t)NROWS * HID];    // 8 MB
__device__ float g_gge[BB * HID];              // global graph embedding accumulator
__device__ float g_scores[BB * JJ];            // actor scores before softmax
__device__ int   g_done[BB];                   // per-batch completion counters

__device__ __forceinline__ void cp_async16(void* smem_dst, const void* gmem_src) {
    unsigned sa = (unsigned)__cvta_generic_to_shared(smem_dst);
    asm volatile("cp.async.cg.shared.global [%0], [%1], 16;\n"
                 :: "r"(sa), "l"(gmem_src));
}
__device__ __forceinline__ void cp_commit() {
    asm volatile("cp.async.commit_group;\n");
}
template <int N>
__device__ __forceinline__ void cp_wait() {
    asm volatile("cp.async.wait_group %0;\n" :: "n"(N));
}

// ============================================================================
// Kernel 1 (UNCHANGED, at HBM wall): stream adj once via per-warp cp.async
// ring. Warp-per-row, group-skip, shared-atomic compaction + GIN0 MLP.
// ============================================================================
#define NBUF 3
#define NCHUNK 32
__global__ __launch_bounds__(512) void k1_scan(
    const float* __restrict__ adj, const float* __restrict__ feat,
    const float* __restrict__ w1, const float* __restrict__ b1,
    const float* __restrict__ w2, const float* __restrict__ b2)
{
    __shared__ float s_w2[HID * HID];
    __shared__ uint4 s_buf[16][NBUF][32];
    __shared__ float s_w1[2 * HID];
    __shared__ float s_b1[HID], s_b2[HID];
    __shared__ float s_p[16][2];
    __shared__ float s_z[16][HID];
    __shared__ int   s_cnt[16];

    const int tid  = threadIdx.x;
    const int w    = tid >> 5;
    const int lane = tid & 31;

    for (int i = tid; i < HID * HID; i += 512) s_w2[i] = w2[i];
    if (tid < 2 * HID) s_w1[tid] = w1[tid];
    if (tid < HID) { s_b1[tid] = b1[tid]; s_b2[tid] = b2[tid]; }
    if (lane == 0) s_cnt[w] = 0;
    if (blockIdx.x == 0) {
        if (tid < BB * HID) g_gge[tid] = 0.f;
        if (tid < BB) g_done[tid] = 0;
    }
    __syncwarp();

    const int r = blockIdx.x * 16 + w;
    const int b = r >> 12;
    const float* __restrict__ grow = adj + (size_t)r * NN;
    const float2* __restrict__ f2p = (const float2*)feat + (size_t)b * NN;
    int* __restrict__ irow = g_idx + (size_t)r * CAP;

    float p0 = 0.f, p1 = 0.f;

#define PROC_ELEM(bits, jj) do {                                           \
        if ((bits) != 0u) {                                                \
            const int pos = atomicAdd(&s_cnt[w], 1);                       \
            const bool two = ((bits) == 0x40000000u);                      \
            if (pos < CAP) irow[pos] = (jj) | (two ? 0x80000000 : 0);      \
            const float2 f = f2p[(jj)];                                    \
            const float sv = two ? 2.f : 1.f;                              \
            p0 += sv * f.x; p1 += sv * f.y;                                \
        }                                                                  \
    } while (0)

#define PROC_CHUNK(c) do {                                                 \
        const uint4 v = s_buf[w][(c) % NBUF][lane];                        \
        if (v.x | v.y | v.z | v.w) {                                       \
            const int jb = (c) * 128 + lane * 4;                           \
            PROC_ELEM(v.x, jb + 0);                                        \
            PROC_ELEM(v.y, jb + 1);                                        \
            PROC_ELEM(v.z, jb + 2);                                        \
            PROC_ELEM(v.w, jb + 3);                                        \
        }                                                                  \
    } while (0)

    #pragma unroll
    for (int c = 0; c < NBUF; c++) {
        cp_async16(&s_buf[w][c][lane], grow + c * 128 + lane * 4);
        cp_commit();
    }
    #pragma unroll 1
    for (int c = 0; c < NCHUNK - NBUF; c++) {
        cp_wait<NBUF - 1>();
        PROC_CHUNK(c);
        cp_async16(&s_buf[w][(c + NBUF) % NBUF][lane],
                   grow + (c + NBUF) * 128 + lane * 4);
        cp_commit();
    }
    cp_wait<0>();
    #pragma unroll
    for (int c = NCHUNK - NBUF; c < NCHUNK; c++) PROC_CHUNK(c);
#undef PROC_CHUNK
#undef PROC_ELEM

    #pragma unroll
    for (int o = 16; o > 0; o >>= 1) {
        p0 += __shfl_down_sync(0xffffffffu, p0, o);
        p1 += __shfl_down_sync(0xffffffffu, p1, o);
    }
    __syncwarp();
    if (lane == 0) {
        s_p[w][0] = p0; s_p[w][1] = p1;
        g_cnt[r] = min(s_cnt[w], CAP);
    }
    __syncthreads();

    const int h = tid & 63;
    const int slot = tid >> 6;
    #pragma unroll
    for (int t = 0; t < 2; t++) {
        const int rr = slot + t * 8;
        const float z = s_b1[h] + s_p[rr][0] * s_w1[h] + s_p[rr][1] * s_w1[HID + h];
        s_z[rr][h] = fmaxf(z, 0.f);
    }
    __syncthreads();
    #pragma unroll
    for (int t = 0; t < 2; t++) {
        const int rr = slot + t * 8;
        float acc = s_b2[h];
        #pragma unroll
        for (int k = 0; k < HID; k++) acc += s_z[rr][k] * s_w2[k * HID + h];
        g_h1[(size_t)(blockIdx.x * 16 + rr) * HID + h] = fmaxf(acc, 0.f);
    }
}

// ============================================================================
// Kernel 2a: GATHER ONLY. 8 warps x 4 nodes interleaved per 256-thread block,
// zero smem -> max occupancy. pooled sums to g_pool. 1024 blocks.
// ============================================================================
__global__ __launch_bounds__(256) void k2a_gather()
{
    const int wid = threadIdx.x >> 5, lane = threadIdx.x & 31;
    const int base = blockIdx.x * 32;
    const int b = base >> 12;
    const float2* __restrict__ h1v = (const float2*)g_h1 + ((size_t)b << 12) * 32;
    float2* __restrict__ outp = (float2*)g_pool;

    const int ln0 = base + wid * 4;
    int cnt[4]; const int* ip[4];
    #pragma unroll
    for (int i = 0; i < 4; i++) {
        cnt[i] = g_cnt[ln0 + i];
        ip[i]  = g_idx + (size_t)(ln0 + i) * CAP;
    }
    float ax[4] = {0.f, 0.f, 0.f, 0.f}, ay[4] = {0.f, 0.f, 0.f, 0.f};
    const int maxc = max(max(cnt[0], cnt[1]), max(cnt[2], cnt[3]));
    for (int k0 = 0; k0 < maxc; k0 += 32) {
        int enc[4];
        #pragma unroll
        for (int i = 0; i < 4; i++)
            enc[i] = (k0 + lane < cnt[i]) ? ip[i][k0 + lane] : 0;
        const int rem = min(maxc - k0, 32);
        #pragma unroll 2
        for (int n = 0; n < rem; n++) {
            #pragma unroll
            for (int i = 0; i < 4; i++) {
                const int e = __shfl_sync(0xffffffffu, enc[i], n);
                if (k0 + n < cnt[i]) {           // warp-uniform predicate
                    const float2 v = h1v[(size_t)(e & 0x7fffffff) * 32 + lane];
                    const float s = (e < 0) ? 2.f : 1.f;
                    ax[i] += s * v.x; ay[i] += s * v.y;
                }
            }
        }
    }
    #pragma unroll
    for (int i = 0; i < 4; i++)
        outp[(size_t)(ln0 + i) * 32 + lane] = make_float2(ax[i], ay[i]);
}

// ============================================================================
// Kernel 2b: GIN1 MLP, register-stationary weights.
// Thread owns (h = tid&63, fgroup = tid>>6); w1/w2 slices in 32 registers.
// 64 nodes per block in 4 batches of 16; x reads are warp-uniform LDS.128
// broadcasts -> FMA-bound. Cross-fgroup reduce via 16KB partials buffer.
// Fused graph pooling. 512 blocks x 256 threads.
// ============================================================================
#define NPB 64
#define BATCH 16
__global__ __launch_bounds__(256) void k2b_mlp(
    const float* __restrict__ w1, const float* __restrict__ b1,
    const float* __restrict__ w2, const float* __restrict__ b2,
    const float* __restrict__ gp)
{
    __shared__ __align__(16) float s_x[BATCH][HID];        // 4 KB
    __shared__ __align__(16) float s_part[4][BATCH][HID];  // 16 KB
    __shared__ __align__(16) float s_z[BATCH][HID];        // 4 KB
    __shared__ float s_acc[HID];

    const int tid = threadIdx.x;
    const int h   = tid & 63;
    const int fg  = tid >> 6;            // 0..3

    float w1r[16], w2r[16];
    #pragma unroll
    for (int i = 0; i < 16; i++) {
        w1r[i] = w1[(fg * 16 + i) * HID + h];
        w2r[i] = w2[(fg * 16 + i) * HID + h];
    }
    if (tid < HID) s_acc[tid] = 0.f;

    const int base = blockIdx.x * NPB;
    const int b = base >> 12;
    float gacc = 0.f;

    #pragma unroll 1
    for (int nb = 0; nb < NPB / BATCH; nb++) {
        const int n0 = base + nb * BATCH;
        // load x batch: 16 nodes x 64 floats, coalesced float4
        {
            const int n = tid >> 4, f4 = (tid & 15) * 4;
            const float4 xv = *(const float4*)&g_pool[(size_t)(n0 + n) * HID + f4];
            __syncthreads();             // prev batch's s_part reads done
            *(float4*)&s_x[n][f4] = xv;
        }
        __syncthreads();

        // layer 1 partials: a = sum over my 16 f of x[n][f]*w1r
        #pragma unroll
        for (int n = 0; n < BATCH; n++) {
            float a = 0.f;
            #pragma unroll
            for (int q = 0; q < 4; q++) {
                const float4 xv = *(const float4*)&s_x[n][fg * 16 + q * 4];
                a += xv.x * w1r[q * 4] + xv.y * w1r[q * 4 + 1]
                   + xv.z * w1r[q * 4 + 2] + xv.w * w1r[q * 4 + 3];
            }
            s_part[fg][n][h] = a;
        }
        __syncthreads();

        // reduce + bias + relu -> z
        #pragma unroll
        for (int k = 0; k < 4; k++) {
            const int p = tid + 256 * k;
            const int n = p >> 6, hh = p & 63;
            const float z = b1[hh] + ((s_part[0][n][hh] + s_part[1][n][hh])
                                    + (s_part[2][n][hh] + s_part[3][n][hh]));
            s_z[n][hh] = fmaxf(z, 0.f);
        }
        __syncthreads();

        // layer 2 partials
        #pragma unroll
        for (int n = 0; n < BATCH; n++) {
            float a = 0.f;
            #pragma unroll
            for (int q = 0; q < 4; q++) {
                const float4 zv = *(const float4*)&s_z[n][fg * 16 + q * 4];
                a += zv.x * w2r[q * 4] + zv.y * w2r[q * 4 + 1]
                   + zv.z * w2r[q * 4 + 2] + zv.w * w2r[q * 4 + 3];
            }
            s_part[fg][n][h] = a;
        }
        __syncthreads();

        // reduce + bias + relu -> h2 (gmem) + pooling
        #pragma unroll
        for (int k = 0; k < 4; k++) {
            const int p = tid + 256 * k;
            const int n = p >> 6, hh = p & 63;
            float v = b2[hh] + ((s_part[0][n][hh] + s_part[1][n][hh])
                              + (s_part[2][n][hh] + s_part[3][n][hh]));
            v = fmaxf(v, 0.f);
            g_h2[(size_t)(n0 + n) * HID + hh] = v;
            gacc += gp[n0 + n] * v;      // hh == h for all k (256k % 64 == 0)
        }
    }
    atomicAdd(&s_acc[h], gacc);
    __syncthreads();
    if (tid < HID) atomicAdd(&g_gge[b * HID + tid], s_acc[tid]);
}

// ============================================================================
// Kernel 3 (unchanged): actor MLP warp-per-job + fused masked softmax.
// ============================================================================
__global__ __launch_bounds__(128) void k3_actor(
    const int* __restrict__ cand, const int* __restrict__ mask,
    const float* __restrict__ pmi,
    const float* __restrict__ w1, const float* __restrict__ b1,
    const float* __restrict__ w2, const float* __restrict__ b2,
    const float* __restrict__ w3, const float* __restrict__ b3,
    float* __restrict__ out)
{
    __shared__ float s_x[4][3 * HID];
    __shared__ float s_t[4][HID];
    __shared__ float s_red[JJ];
    __shared__ int   s_ticket;

    const int w    = threadIdx.x >> 5;
    const int lane = threadIdx.x & 31;
    const int job  = blockIdx.x * 4 + w;
    const int bb   = job >> 7;
    const int j    = job & 127;

    const int c = cand[bb * JJ + j];
    const float2* e2 = (const float2*)(g_h2 + ((size_t)bb * NN + c) * HID);
    const float2* g2 = (const float2*)(g_gge + bb * HID);
    const float2* p2 = (const float2*)pmi;
    float2 t;
    t = e2[lane]; s_x[w][2 * lane] = t.x; s_x[w][2 * lane + 1] = t.y;
    t = g2[lane]; s_x[w][HID + 2 * lane] = t.x; s_x[w][HID + 2 * lane + 1] = t.y;
    t = p2[lane]; s_x[w][2 * HID + 2 * lane] = t.x; s_x[w][2 * HID + 2 * lane + 1] = t.y;
    __syncwarp();

    float a0 = b1[lane], a1 = b1[lane + 32];
    #pragma unroll 8
    for (int f = 0; f < 3 * HID; f++) {
        const float xv = s_x[w][f];
        a0 += xv * w1[f * HID + lane];
        a1 += xv * w1[f * HID + lane + 32];
    }
    s_t[w][lane] = tanhf(a0); s_t[w][lane + 32] = tanhf(a1);
    __syncwarp();

    float c0 = b2[lane], c1 = b2[lane + 32];
    #pragma unroll 8
    for (int k = 0; k < HID; k++) {
        const float xv = s_t[w][k];
        c0 += xv * w2[k * HID + lane];
        c1 += xv * w2[k * HID + lane + 32];
    }

    float part = tanhf(c0) * w3[lane] + tanhf(c1) * w3[lane + 32];
    #pragma unroll
    for (int o = 16; o > 0; o >>= 1)
        part += __shfl_down_sync(0xffffffffu, part, o);
    if (lane == 0) {
        float score = (part + b3[0]) * 10.0f;
        if (mask[bb * JJ + j]) score = -INFINITY;
        g_scores[job] = score;
        __threadfence();
    }
    __syncthreads();
    if (threadIdx.x == 0)
        s_ticket = atomicAdd(&g_done[bb], 1);
    __syncthreads();

    if (s_ticket == 31) {
        __threadfence();
        const int jj = threadIdx.x;
        const float sc = __ldcg(&g_scores[bb * JJ + jj]);
        s_red[jj] = sc; __syncthreads();
        for (int s = JJ / 2; s > 0; s >>= 1) {
            if (jj < s) s_red[jj] = fmaxf(s_red[jj], s_red[jj + s]);
            __syncthreads();
        }
        const float mx = s_red[0]; __syncthreads();
        const float e = expf(sc - mx);
        s_red[jj] = e; __syncthreads();
        for (int s = JJ / 2; s > 0; s >>= 1) {
            if (jj < s) s_red[jj] += s_red[jj + s];
            __syncthreads();
        }
        out[bb * JJ + jj] = e / s_red[0];
    }
}

// ============================================================================
extern "C" void kernel_launch(void* const* d_in, const int* in_sizes, int n_in,
                              void* d_out, int out_size)
{
    const float* features   = (const float*)d_in[0];
    const float* graph_pool = (const float*)d_in[1];
    const float* adj        = (const float*)d_in[2];
    const int*   candidate  = (const int*)d_in[3];
    const int*   mask       = (const int*)d_in[4];
    const float* g0w1 = (const float*)d_in[5];
    const float* g0b1 = (const float*)d_in[6];
    const float* g0w2 = (const float*)d_in[7];
    const float* g0b2 = (const float*)d_in[8];
    const float* g1w1 = (const float*)d_in[9];
    const float* g1b1 = (const float*)d_in[10];
    const float* g1w2 = (const float*)d_in[11];
    const float* g1b2 = (const float*)d_in[12];
    const float* pmi  = (const float*)d_in[13];
    const float* aw1  = (const float*)d_in[14];
    const float* ab1  = (const float*)d_in[15];
    const float* aw2  = (const float*)d_in[16];
    const float* ab2  = (const float*)d_in[17];
    const float* aw3  = (const float*)d_in[18];
    const float* ab3  = (const float*)d_in[19];
    float* out = (float*)d_out;

    k1_scan<<<NROWS / 16, 512>>>(adj, features, g0w1, g0b1, g0w2, g0b2);
    k2a_gather<<<NROWS / 32, 256>>>();
    k2b_mlp<<<NROWS / NPB, 256>>>(g1w1, g1b1, g1w2, g1b2, graph_pool);
    k3_actor<<<BB * JJ / 4, 128>>>(candidate, mask, pmi,
                                   aw1, ab1, aw2, ab2, aw3, ab3, out);
}

// round 9
// speedup vs baseline: 1.4023x; 1.1713x over previous
#include <cuda_runtime.h>
#include <cstdint>
#include <math.h>

#define BB   8
#define NN   4096
#define HID  64
#define JJ   128
#define CAP  96
#define NROWS (BB*NN)   // 32768

// ---- scratch (device globals; no allocation allowed) ----
__device__ int   g_cnt[NROWS];
__device__ int   g_idx[(size_t)NROWS * CAP];   // packed: col | (val==2 ? 0x80000000 : 0)
__device__ float g_h1[(size_t)NROWS * HID];    // 8 MB
__device__ float g_pool[(size_t)NROWS * HID];  // 8 MB (layer-1 neighbor sums)
__device__ float g_h2[(size_t)NROWS * HID];    // 8 MB
__device__ float g_gge[BB * HID];              // global graph embedding accumulator
__device__ float g_scores[BB * JJ];            // actor scores before softmax
__device__ int   g_done[BB];                   // per-batch completion counters

__device__ __forceinline__ void cp_async16(void* smem_dst, const void* gmem_src) {
    unsigned sa = (unsigned)__cvta_generic_to_shared(smem_dst);
    asm volatile("cp.async.cg.shared.global [%0], [%1], 16;\n"
                 :: "r"(sa), "l"(gmem_src));
}
__device__ __forceinline__ void cp_commit() {
    asm volatile("cp.async.commit_group;\n");
}
template <int N>
__device__ __forceinline__ void cp_wait() {
    asm volatile("cp.async.wait_group %0;\n" :: "n"(N));
}

// ============================================================================
// Kernel 1 (UNCHANGED, at HBM wall): stream adj once via per-warp cp.async
// ring. Warp-per-row, group-skip, shared-atomic compaction + GIN0 MLP.
// ============================================================================
#define NBUF 3
#define NCHUNK 32
__global__ __launch_bounds__(512) void k1_scan(
    const float* __restrict__ adj, const float* __restrict__ feat,
    const float* __restrict__ w1, const float* __restrict__ b1,
    const float* __restrict__ w2, const float* __restrict__ b2)
{
    __shared__ float s_w2[HID * HID];
    __shared__ uint4 s_buf[16][NBUF][32];
    __shared__ float s_w1[2 * HID];
    __shared__ float s_b1[HID], s_b2[HID];
    __shared__ float s_p[16][2];
    __shared__ float s_z[16][HID];
    __shared__ int   s_cnt[16];

    const int tid  = threadIdx.x;
    const int w    = tid >> 5;
    const int lane = tid & 31;

    for (int i = tid; i < HID * HID; i += 512) s_w2[i] = w2[i];
    if (tid < 2 * HID) s_w1[tid] = w1[tid];
    if (tid < HID) { s_b1[tid] = b1[tid]; s_b2[tid] = b2[tid]; }
    if (lane == 0) s_cnt[w] = 0;
    if (blockIdx.x == 0) {
        if (tid < BB * HID) g_gge[tid] = 0.f;
        if (tid < BB) g_done[tid] = 0;
    }
    __syncwarp();

    const int r = blockIdx.x * 16 + w;
    const int b = r >> 12;
    const float* __restrict__ grow = adj + (size_t)r * NN;
    const float2* __restrict__ f2p = (const float2*)feat + (size_t)b * NN;
    int* __restrict__ irow = g_idx + (size_t)r * CAP;

    float p0 = 0.f, p1 = 0.f;

#define PROC_ELEM(bits, jj) do {                                           \
        if ((bits) != 0u) {                                                \
            const int pos = atomicAdd(&s_cnt[w], 1);                       \
            const bool two = ((bits) == 0x40000000u);                      \
            if (pos < CAP) irow[pos] = (jj) | (two ? 0x80000000 : 0);      \
            const float2 f = f2p[(jj)];                                    \
            const float sv = two ? 2.f : 1.f;                              \
            p0 += sv * f.x; p1 += sv * f.y;                                \
        }                                                                  \
    } while (0)

#define PROC_CHUNK(c) do {                                                 \
        const uint4 v = s_buf[w][(c) % NBUF][lane];                        \
        if (v.x | v.y | v.z | v.w) {                                       \
            const int jb = (c) * 128 + lane * 4;                           \
            PROC_ELEM(v.x, jb + 0);                                        \
            PROC_ELEM(v.y, jb + 1);                                        \
            PROC_ELEM(v.z, jb + 2);                                        \
            PROC_ELEM(v.w, jb + 3);                                        \
        }                                                                  \
    } while (0)

    #pragma unroll
    for (int c = 0; c < NBUF; c++) {
        cp_async16(&s_buf[w][c][lane], grow + c * 128 + lane * 4);
        cp_commit();
    }
    #pragma unroll 1
    for (int c = 0; c < NCHUNK - NBUF; c++) {
        cp_wait<NBUF - 1>();
        PROC_CHUNK(c);
        cp_async16(&s_buf[w][(c + NBUF) % NBUF][lane],
                   grow + (c + NBUF) * 128 + lane * 4);
        cp_commit();
    }
    cp_wait<0>();
    #pragma unroll
    for (int c = NCHUNK - NBUF; c < NCHUNK; c++) PROC_CHUNK(c);
#undef PROC_CHUNK
#undef PROC_ELEM

    #pragma unroll
    for (int o = 16; o > 0; o >>= 1) {
        p0 += __shfl_down_sync(0xffffffffu, p0, o);
        p1 += __shfl_down_sync(0xffffffffu, p1, o);
    }
    __syncwarp();
    if (lane == 0) {
        s_p[w][0] = p0; s_p[w][1] = p1;
        g_cnt[r] = min(s_cnt[w], CAP);
    }
    __syncthreads();

    const int h = tid & 63;
    const int slot = tid >> 6;
    #pragma unroll
    for (int t = 0; t < 2; t++) {
        const int rr = slot + t * 8;
        const float z = s_b1[h] + s_p[rr][0] * s_w1[h] + s_p[rr][1] * s_w1[HID + h];
        s_z[rr][h] = fmaxf(z, 0.f);
    }
    __syncthreads();
    #pragma unroll
    for (int t = 0; t < 2; t++) {
        const int rr = slot + t * 8;
        float acc = s_b2[h];
        #pragma unroll
        for (int k = 0; k < HID; k++) acc += s_z[rr][k] * s_w2[k * HID + h];
        g_h1[(size_t)(blockIdx.x * 16 + rr) * HID + h] = fmaxf(acc, 0.f);
    }
}

// ============================================================================
// Kernel 2a (UNCHANGED): gather-only, zero smem, 8 warps x 4 nodes.
// ============================================================================
__global__ __launch_bounds__(256) void k2a_gather()
{
    const int wid = threadIdx.x >> 5, lane = threadIdx.x & 31;
    const int base = blockIdx.x * 32;
    const int b = base >> 12;
    const float2* __restrict__ h1v = (const float2*)g_h1 + ((size_t)b << 12) * 32;
    float2* __restrict__ outp = (float2*)g_pool;

    const int ln0 = base + wid * 4;
    int cnt[4]; const int* ip[4];
    #pragma unroll
    for (int i = 0; i < 4; i++) {
        cnt[i] = g_cnt[ln0 + i];
        ip[i]  = g_idx + (size_t)(ln0 + i) * CAP;
    }
    float ax[4] = {0.f, 0.f, 0.f, 0.f}, ay[4] = {0.f, 0.f, 0.f, 0.f};
    const int maxc = max(max(cnt[0], cnt[1]), max(cnt[2], cnt[3]));
    for (int k0 = 0; k0 < maxc; k0 += 32) {
        int enc[4];
        #pragma unroll
        for (int i = 0; i < 4; i++)
            enc[i] = (k0 + lane < cnt[i]) ? ip[i][k0 + lane] : 0;
        const int rem = min(maxc - k0, 32);
        #pragma unroll 2
        for (int n = 0; n < rem; n++) {
            #pragma unroll
            for (int i = 0; i < 4; i++) {
                const int e = __shfl_sync(0xffffffffu, enc[i], n);
                if (k0 + n < cnt[i]) {
                    const float2 v = h1v[(size_t)(e & 0x7fffffff) * 32 + lane];
                    const float s = (e < 0) ? 2.f : 1.f;
                    ax[i] += s * v.x; ay[i] += s * v.y;
                }
            }
        }
    }
    #pragma unroll
    for (int i = 0; i < 4; i++)
        outp[(size_t)(ln0 + i) * 32 + lane] = make_float2(ax[i], ay[i]);
}

// ============================================================================
// Kernel 2b (UNCHANGED): GIN1 MLP, register-stationary weights + pooling.
// ============================================================================
#define NPB 64
#define BATCH 16
__global__ __launch_bounds__(256) void k2b_mlp(
    const float* __restrict__ w1, const float* __restrict__ b1,
    const float* __restrict__ w2, const float* __restrict__ b2,
    const float* __restrict__ gp)
{
    __shared__ __align__(16) float s_x[BATCH][HID];
    __shared__ __align__(16) float s_part[4][BATCH][HID];
    __shared__ __align__(16) float s_z[BATCH][HID];
    __shared__ float s_acc[HID];

    const int tid = threadIdx.x;
    const int h   = tid & 63;
    const int fg  = tid >> 6;

    float w1r[16], w2r[16];
    #pragma unroll
    for (int i = 0; i < 16; i++) {
        w1r[i] = w1[(fg * 16 + i) * HID + h];
        w2r[i] = w2[(fg * 16 + i) * HID + h];
    }
    if (tid < HID) s_acc[tid] = 0.f;

    const int base = blockIdx.x * NPB;
    const int b = base >> 12;
    float gacc = 0.f;

    #pragma unroll 1
    for (int nb = 0; nb < NPB / BATCH; nb++) {
        const int n0 = base + nb * BATCH;
        {
            const int n = tid >> 4, f4 = (tid & 15) * 4;
            const float4 xv = *(const float4*)&g_pool[(size_t)(n0 + n) * HID + f4];
            __syncthreads();
            *(float4*)&s_x[n][f4] = xv;
        }
        __syncthreads();

        #pragma unroll
        for (int n = 0; n < BATCH; n++) {
            float a = 0.f;
            #pragma unroll
            for (int q = 0; q < 4; q++) {
                const float4 xv = *(const float4*)&s_x[n][fg * 16 + q * 4];
                a += xv.x * w1r[q * 4] + xv.y * w1r[q * 4 + 1]
                   + xv.z * w1r[q * 4 + 2] + xv.w * w1r[q * 4 + 3];
            }
            s_part[fg][n][h] = a;
        }
        __syncthreads();

        #pragma unroll
        for (int k = 0; k < 4; k++) {
            const int p = tid + 256 * k;
            const int n = p >> 6, hh = p & 63;
            const float z = b1[hh] + ((s_part[0][n][hh] + s_part[1][n][hh])
                                    + (s_part[2][n][hh] + s_part[3][n][hh]));
            s_z[n][hh] = fmaxf(z, 0.f);
        }
        __syncthreads();

        #pragma unroll
        for (int n = 0; n < BATCH; n++) {
            float a = 0.f;
            #pragma unroll
            for (int q = 0; q < 4; q++) {
                const float4 zv = *(const float4*)&s_z[n][fg * 16 + q * 4];
                a += zv.x * w2r[q * 4] + zv.y * w2r[q * 4 + 1]
                   + zv.z * w2r[q * 4 + 2] + zv.w * w2r[q * 4 + 3];
            }
            s_part[fg][n][h] = a;
        }
        __syncthreads();

        #pragma unroll
        for (int k = 0; k < 4; k++) {
            const int p = tid + 256 * k;
            const int n = p >> 6, hh = p & 63;
            float v = b2[hh] + ((s_part[0][n][hh] + s_part[1][n][hh])
                              + (s_part[2][n][hh] + s_part[3][n][hh]));
            v = fmaxf(v, 0.f);
            g_h2[(size_t)(n0 + n) * HID + hh] = v;
            gacc += gp[n0 + n] * v;
        }
    }
    atomicAdd(&s_acc[h], gacc);
    __syncthreads();
    if (tid < HID) atomicAdd(&g_gge[b * HID + tid], s_acc[tid]);
}

// ============================================================================
// Kernel 3 (REWRITTEN): 32 blocks x 256 threads; block = (batch, 32 jobs).
//   - batch-invariant layer-1 part (gge/pmi @ w1 + b1) computed per block
//   - w1 emb-slice + w2 in smem; thread = (job, 8 outputs)
//   - fused masked softmax via ticket (4 blocks per batch)
// ============================================================================
#define JPB 32
#define XS  68   // padded stride: conflict-free x/t reads
__global__ __launch_bounds__(256) void k3_actor(
    const int* __restrict__ cand, const int* __restrict__ mask,
    const float* __restrict__ pmi,
    const float* __restrict__ w1, const float* __restrict__ b1,
    const float* __restrict__ w2, const float* __restrict__ b2,
    const float* __restrict__ w3, const float* __restrict__ b3,
    float* __restrict__ out)
{
    __shared__ __align__(16) float s_w1[HID * HID];   // 16 KB (w1 rows 0..63)
    __shared__ __align__(16) float s_w2[HID * HID];   // 16 KB
    __shared__ __align__(16) float s_x[JPB * XS];     // 8.5 KB (x, then t)
    __shared__ float s_bp[4][HID];
    __shared__ float s_base[HID];
    __shared__ float s_red[JJ];
    __shared__ int   s_ticket;

    const int tid  = threadIdx.x;
    const int bb   = blockIdx.x >> 2;                 // batch
    const int jb0  = (blockIdx.x & 3) * JPB;          // first job of this block
    const int job  = tid >> 3;                        // 0..31
    const int hg   = tid & 7;
    const int h0   = hg * 8;

    // ---- load weights to smem (coalesced float4) ----
    {
        const float4* w1v = (const float4*)w1;        // rows 0..63 contiguous
        const float4* w2v = (const float4*)w2;
        float4* d1 = (float4*)s_w1; float4* d2 = (float4*)s_w2;
        #pragma unroll
        for (int i = 0; i < 4; i++) {
            d1[tid + 256 * i] = w1v[tid + 256 * i];
            d2[tid + 256 * i] = w2v[tid + 256 * i];
        }
    }

    // ---- batch-invariant base: b1 + gge@w1[64:128] + pmi@w1[128:192] ----
    {
        const int q = tid >> 6, h = tid & 63;
        const float* xs = (q < 2) ? (g_gge + bb * HID) : pmi;
        const int f0 = (q & 1) * 32;
        const int row0 = 64 + (q >> 1) * 64 + f0;
        float a = 0.f;
        #pragma unroll 8
        for (int i = 0; i < 32; i++)
            a += xs[f0 + i] * w1[(row0 + i) * HID + h];
        s_bp[q][h] = a;
    }

    // ---- gather candidate embeddings into s_x ----
    {
        const int c = cand[bb * JJ + jb0 + job];
        const float4* e4 = (const float4*)(g_h2 + ((size_t)bb * NN + c) * HID);
        *(float4*)&s_x[job * XS + h0]     = e4[hg * 2];
        *(float4*)&s_x[job * XS + h0 + 4] = e4[hg * 2 + 1];
    }
    if (tid == 0) s_ticket = -1;
    __syncthreads();

    if (tid < HID)
        s_base[tid] = b1[tid] + ((s_bp[0][tid] + s_bp[1][tid])
                               + (s_bp[2][tid] + s_bp[3][tid]));
    __syncthreads();

    // ---- layer 1: a = tanh(base + emb @ w1[0:64]) ----
    float a[8];
    #pragma unroll
    for (int i = 0; i < 8; i++) a[i] = s_base[h0 + i];
    #pragma unroll 8
    for (int f = 0; f < HID; f++) {
        const float xv = s_x[job * XS + f];
        const float4 wA = *(const float4*)&s_w1[f * HID + h0];
        const float4 wB = *(const float4*)&s_w1[f * HID + h0 + 4];
        a[0] += xv * wA.x; a[1] += xv * wA.y; a[2] += xv * wA.z; a[3] += xv * wA.w;
        a[4] += xv * wB.x; a[5] += xv * wB.y; a[6] += xv * wB.z; a[7] += xv * wB.w;
    }
    __syncthreads();                      // all x reads done
    #pragma unroll
    for (int i = 0; i < 8; i++) s_x[job * XS + h0 + i] = tanhf(a[i]);
    __syncthreads();

    // ---- layer 2: c = tanh(t @ w2 + b2) ----
    #pragma unroll
    for (int i = 0; i < 8; i++) a[i] = b2[h0 + i];
    #pragma unroll 8
    for (int f = 0; f < HID; f++) {
        const float tv = s_x[job * XS + f];
        const float4 wA = *(const float4*)&s_w2[f * HID + h0];
        const float4 wB = *(const float4*)&s_w2[f * HID + h0 + 4];
        a[0] += tv * wA.x; a[1] += tv * wA.y; a[2] += tv * wA.z; a[3] += tv * wA.w;
        a[4] += tv * wB.x; a[5] += tv * wB.y; a[6] += tv * wB.z; a[7] += tv * wB.w;
    }

    // ---- layer 3 + mask ----
    float part = 0.f;
    #pragma unroll
    for (int i = 0; i < 8; i++) part += tanhf(a[i]) * w3[h0 + i];
    part += __shfl_down_sync(0xffffffffu, part, 4, 8);
    part += __shfl_down_sync(0xffffffffu, part, 2, 8);
    part += __shfl_down_sync(0xffffffffu, part, 1, 8);
    if (hg == 0) {
        const int jg = jb0 + job;
        float score = (part + b3[0]) * 10.0f;
        if (mask[bb * JJ + jg]) score = -INFINITY;
        g_scores[bb * JJ + jg] = score;
        __threadfence();
    }
    __syncthreads();
    if (tid == 0) s_ticket = atomicAdd(&g_done[bb], 1);
    __syncthreads();

    if (s_ticket == 3) {                  // last of 4 blocks for this batch
        __threadfence();
        const float sc = (tid < JJ) ? __ldcg(&g_scores[bb * JJ + tid]) : -INFINITY;
        if (tid < JJ) s_red[tid] = sc;
        __syncthreads();
        for (int s = JJ / 2; s > 0; s >>= 1) {
            if (tid < s) s_red[tid] = fmaxf(s_red[tid], s_red[tid + s]);
            __syncthreads();
        }
        const float mx = s_red[0]; __syncthreads();
        const float e = (tid < JJ) ? expf(sc - mx) : 0.f;
        if (tid < JJ) s_red[tid] = e;
        __syncthreads();
        for (int s = JJ / 2; s > 0; s >>= 1) {
            if (tid < s) s_red[tid] += s_red[tid + s];
            __syncthreads();
        }
        if (tid < JJ) out[bb * JJ + tid] = e / s_red[0];
    }
}

// ============================================================================
extern "C" void kernel_launch(void* const* d_in, const int* in_sizes, int n_in,
                              void* d_out, int out_size)
{
    const float* features   = (const float*)d_in[0];
    const float* graph_pool = (const float*)d_in[1];
    const float* adj        = (const float*)d_in[2];
    const int*   candidate  = (const int*)d_in[3];
    const int*   mask       = (const int*)d_in[4];
    const float* g0w1 = (const float*)d_in[5];
    const float* g0b1 = (const float*)d_in[6];
    const float* g0w2 = (const float*)d_in[7];
    const float* g0b2 = (const float*)d_in[8];
    const float* g1w1 = (const float*)d_in[9];
    const float* g1b1 = (const float*)d_in[10];
    const float* g1w2 = (const float*)d_in[11];
    const float* g1b2 = (const float*)d_in[12];
    const float* pmi  = (const float*)d_in[13];
    const float* aw1  = (const float*)d_in[14];
    const float* ab1  = (const float*)d_in[15];
    const float* aw2  = (const float*)d_in[16];
    const float* ab2  = (const float*)d_in[17];
    const float* aw3  = (const float*)d_in[18];
    const float* ab3  = (const float*)d_in[19];
    float* out = (float*)d_out;

    k1_scan<<<NROWS / 16, 512>>>(adj, features, g0w1, g0b1, g0w2, g0b2);
    k2a_gather<<<NROWS / 32, 256>>>();
    k2b_mlp<<<NROWS / NPB, 256>>>(g1w1, g1b1, g1w2, g1b2, graph_pool);
    k3_actor<<<BB * JJ / JPB, 256>>>(candidate, mask, pmi,
                                     aw1, ab1, aw2, ab2, aw3, ab3, out);
}

// round 10
// speedup vs baseline: 1.4633x; 1.0435x over previous
#include <cuda_runtime.h>
#include <cstdint>
#include <math.h>

#define BB   8
#define NN   4096
#define HID  64
#define JJ   128
#define CAP  96
#define NROWS (BB*NN)   // 32768

// ---- scratch (device globals; no allocation allowed) ----
__device__ int   g_cnt[NROWS];
__device__ int   g_idx[(size_t)NROWS * CAP];   // packed: col | (val==2 ? 0x80000000 : 0)
__device__ float g_h1[(size_t)NROWS * HID];    // 8 MB
__device__ float g_pool[(size_t)NROWS * HID];  // 8 MB (layer-1 neighbor sums)
__device__ float g_h2[(size_t)NROWS * HID];    // 8 MB
__device__ float g_gge[BB * HID];              // global graph embedding accumulator
__device__ float g_scores[BB * JJ];            // actor scores before softmax
__device__ int   g_done[BB];                   // per-batch completion counters

__device__ __forceinline__ void cp_async16(void* smem_dst, const void* gmem_src) {
    unsigned sa = (unsigned)__cvta_generic_to_shared(smem_dst);
    asm volatile("cp.async.cg.shared.global [%0], [%1], 16;\n"
                 :: "r"(sa), "l"(gmem_src));
}
__device__ __forceinline__ void cp_commit() {
    asm volatile("cp.async.commit_group;\n");
}
template <int N>
__device__ __forceinline__ void cp_wait() {
    asm volatile("cp.async.wait_group %0;\n" :: "n"(N));
}

// ============================================================================
// Kernel 1 (UNCHANGED, at HBM wall): stream adj once via per-warp cp.async
// ring. Warp-per-row, group-skip, shared-atomic compaction + GIN0 MLP.
// ============================================================================
#define NBUF 3
#define NCHUNK 32
__global__ __launch_bounds__(512) void k1_scan(
    const float* __restrict__ adj, const float* __restrict__ feat,
    const float* __restrict__ w1, const float* __restrict__ b1,
    const float* __restrict__ w2, const float* __restrict__ b2)
{
    __shared__ float s_w2[HID * HID];
    __shared__ uint4 s_buf[16][NBUF][32];
    __shared__ float s_w1[2 * HID];
    __shared__ float s_b1[HID], s_b2[HID];
    __shared__ float s_p[16][2];
    __shared__ float s_z[16][HID];
    __shared__ int   s_cnt[16];

    const int tid  = threadIdx.x;
    const int w    = tid >> 5;
    const int lane = tid & 31;

    for (int i = tid; i < HID * HID; i += 512) s_w2[i] = w2[i];
    if (tid < 2 * HID) s_w1[tid] = w1[tid];
    if (tid < HID) { s_b1[tid] = b1[tid]; s_b2[tid] = b2[tid]; }
    if (lane == 0) s_cnt[w] = 0;
    if (blockIdx.x == 0) {
        if (tid < BB * HID) g_gge[tid] = 0.f;
        if (tid < BB) g_done[tid] = 0;
    }
    __syncwarp();

    const int r = blockIdx.x * 16 + w;
    const int b = r >> 12;
    const float* __restrict__ grow = adj + (size_t)r * NN;
    const float2* __restrict__ f2p = (const float2*)feat + (size_t)b * NN;
    int* __restrict__ irow = g_idx + (size_t)r * CAP;

    float p0 = 0.f, p1 = 0.f;

#define PROC_ELEM(bits, jj) do {                                           \
        if ((bits) != 0u) {                                                \
            const int pos = atomicAdd(&s_cnt[w], 1);                       \
            const bool two = ((bits) == 0x40000000u);                      \
            if (pos < CAP) irow[pos] = (jj) | (two ? 0x80000000 : 0);      \
            const float2 f = f2p[(jj)];                                    \
            const float sv = two ? 2.f : 1.f;                              \
            p0 += sv * f.x; p1 += sv * f.y;                                \
        }                                                                  \
    } while (0)

#define PROC_CHUNK(c) do {                                                 \
        const uint4 v = s_buf[w][(c) % NBUF][lane];                        \
        if (v.x | v.y | v.z | v.w) {                                       \
            const int jb = (c) * 128 + lane * 4;                           \
            PROC_ELEM(v.x, jb + 0);                                        \
            PROC_ELEM(v.y, jb + 1);                                        \
            PROC_ELEM(v.z, jb + 2);                                        \
            PROC_ELEM(v.w, jb + 3);                                        \
        }                                                                  \
    } while (0)

    #pragma unroll
    for (int c = 0; c < NBUF; c++) {
        cp_async16(&s_buf[w][c][lane], grow + c * 128 + lane * 4);
        cp_commit();
    }
    #pragma unroll 1
    for (int c = 0; c < NCHUNK - NBUF; c++) {
        cp_wait<NBUF - 1>();
        PROC_CHUNK(c);
        cp_async16(&s_buf[w][(c + NBUF) % NBUF][lane],
                   grow + (c + NBUF) * 128 + lane * 4);
        cp_commit();
    }
    cp_wait<0>();
    #pragma unroll
    for (int c = NCHUNK - NBUF; c < NCHUNK; c++) PROC_CHUNK(c);
#undef PROC_CHUNK
#undef PROC_ELEM

    #pragma unroll
    for (int o = 16; o > 0; o >>= 1) {
        p0 += __shfl_down_sync(0xffffffffu, p0, o);
        p1 += __shfl_down_sync(0xffffffffu, p1, o);
    }
    __syncwarp();
    if (lane == 0) {
        s_p[w][0] = p0; s_p[w][1] = p1;
        g_cnt[r] = min(s_cnt[w], CAP);
    }
    __syncthreads();

    const int h = tid & 63;
    const int slot = tid >> 6;
    #pragma unroll
    for (int t = 0; t < 2; t++) {
        const int rr = slot + t * 8;
        const float z = s_b1[h] + s_p[rr][0] * s_w1[h] + s_p[rr][1] * s_w1[HID + h];
        s_z[rr][h] = fmaxf(z, 0.f);
    }
    __syncthreads();
    #pragma unroll
    for (int t = 0; t < 2; t++) {
        const int rr = slot + t * 8;
        float acc = s_b2[h];
        #pragma unroll
        for (int k = 0; k < HID; k++) acc += s_z[rr][k] * s_w2[k * HID + h];
        g_h1[(size_t)(blockIdx.x * 16 + rr) * HID + h] = fmaxf(acc, 0.f);
    }
}

// ============================================================================
// Kernel 2a (UNCHANGED): gather-only, zero smem, 8 warps x 4 nodes.
// ============================================================================
__global__ __launch_bounds__(256) void k2a_gather()
{
    const int wid = threadIdx.x >> 5, lane = threadIdx.x & 31;
    const int base = blockIdx.x * 32;
    const int b = base >> 12;
    const float2* __restrict__ h1v = (const float2*)g_h1 + ((size_t)b << 12) * 32;
    float2* __restrict__ outp = (float2*)g_pool;

    const int ln0 = base + wid * 4;
    int cnt[4]; const int* ip[4];
    #pragma unroll
    for (int i = 0; i < 4; i++) {
        cnt[i] = g_cnt[ln0 + i];
        ip[i]  = g_idx + (size_t)(ln0 + i) * CAP;
    }
    float ax[4] = {0.f, 0.f, 0.f, 0.f}, ay[4] = {0.f, 0.f, 0.f, 0.f};
    const int maxc = max(max(cnt[0], cnt[1]), max(cnt[2], cnt[3]));
    for (int k0 = 0; k0 < maxc; k0 += 32) {
        int enc[4];
        #pragma unroll
        for (int i = 0; i < 4; i++)
            enc[i] = (k0 + lane < cnt[i]) ? ip[i][k0 + lane] : 0;
        const int rem = min(maxc - k0, 32);
        #pragma unroll 2
        for (int n = 0; n < rem; n++) {
            #pragma unroll
            for (int i = 0; i < 4; i++) {
                const int e = __shfl_sync(0xffffffffu, enc[i], n);
                if (k0 + n < cnt[i]) {
                    const float2 v = h1v[(size_t)(e & 0x7fffffff) * 32 + lane];
                    const float s = (e < 0) ? 2.f : 1.f;
                    ax[i] += s * v.x; ay[i] += s * v.y;
                }
            }
        }
    }
    #pragma unroll
    for (int i = 0; i < 4; i++)
        outp[(size_t)(ln0 + i) * 32 + lane] = make_float2(ax[i], ay[i]);
}

// ============================================================================
// Kernel 2b (UNCHANGED): GIN1 MLP, register-stationary weights + pooling.
// ============================================================================
#define NPB 64
#define BATCH 16
__global__ __launch_bounds__(256) void k2b_mlp(
    const float* __restrict__ w1, const float* __restrict__ b1,
    const float* __restrict__ w2, const float* __restrict__ b2,
    const float* __restrict__ gp)
{
    __shared__ __align__(16) float s_x[BATCH][HID];
    __shared__ __align__(16) float s_part[4][BATCH][HID];
    __shared__ __align__(16) float s_z[BATCH][HID];
    __shared__ float s_acc[HID];

    const int tid = threadIdx.x;
    const int h   = tid & 63;
    const int fg  = tid >> 6;

    float w1r[16], w2r[16];
    #pragma unroll
    for (int i = 0; i < 16; i++) {
        w1r[i] = w1[(fg * 16 + i) * HID + h];
        w2r[i] = w2[(fg * 16 + i) * HID + h];
    }
    if (tid < HID) s_acc[tid] = 0.f;

    const int base = blockIdx.x * NPB;
    const int b = base >> 12;
    float gacc = 0.f;

    #pragma unroll 1
    for (int nb = 0; nb < NPB / BATCH; nb++) {
        const int n0 = base + nb * BATCH;
        {
            const int n = tid >> 4, f4 = (tid & 15) * 4;
            const float4 xv = *(const float4*)&g_pool[(size_t)(n0 + n) * HID + f4];
            __syncthreads();
            *(float4*)&s_x[n][f4] = xv;
        }
        __syncthreads();

        #pragma unroll
        for (int n = 0; n < BATCH; n++) {
            float a = 0.f;
            #pragma unroll
            for (int q = 0; q < 4; q++) {
                const float4 xv = *(const float4*)&s_x[n][fg * 16 + q * 4];
                a += xv.x * w1r[q * 4] + xv.y * w1r[q * 4 + 1]
                   + xv.z * w1r[q * 4 + 2] + xv.w * w1r[q * 4 + 3];
            }
            s_part[fg][n][h] = a;
        }
        __syncthreads();

        #pragma unroll
        for (int k = 0; k < 4; k++) {
            const int p = tid + 256 * k;
            const int n = p >> 6, hh = p & 63;
            const float z = b1[hh] + ((s_part[0][n][hh] + s_part[1][n][hh])
                                    + (s_part[2][n][hh] + s_part[3][n][hh]));
            s_z[n][hh] = fmaxf(z, 0.f);
        }
        __syncthreads();

        #pragma unroll
        for (int n = 0; n < BATCH; n++) {
            float a = 0.f;
            #pragma unroll
            for (int q = 0; q < 4; q++) {
                const float4 zv = *(const float4*)&s_z[n][fg * 16 + q * 4];
                a += zv.x * w2r[q * 4] + zv.y * w2r[q * 4 + 1]
                   + zv.z * w2r[q * 4 + 2] + zv.w * w2r[q * 4 + 3];
            }
            s_part[fg][n][h] = a;
        }
        __syncthreads();

        #pragma unroll
        for (int k = 0; k < 4; k++) {
            const int p = tid + 256 * k;
            const int n = p >> 6, hh = p & 63;
            float v = b2[hh] + ((s_part[0][n][hh] + s_part[1][n][hh])
                              + (s_part[2][n][hh] + s_part[3][n][hh]));
            v = fmaxf(v, 0.f);
            g_h2[(size_t)(n0 + n) * HID + hh] = v;
            gacc += gp[n0 + n] * v;
        }
    }
    atomicAdd(&s_acc[h], gacc);
    __syncthreads();
    if (tid < HID) atomicAdd(&g_gge[b * HID + tid], s_acc[tid]);
}

// ============================================================================
// Kernel 3 (REWRITTEN): 128 blocks x 256 threads; block = (batch, 8 jobs).
//   warp = one job; thread = (job, 2 outputs) -> short serial chains.
//   batch-invariant layer-1 base + smem weights; ticket softmax (16 blk/batch).
// ============================================================================
#define JPB 8
#define XS  66   // padded stride for x/t rows
__global__ __launch_bounds__(256) void k3_actor(
    const int* __restrict__ cand, const int* __restrict__ mask,
    const float* __restrict__ pmi,
    const float* __restrict__ w1, const float* __restrict__ b1,
    const float* __restrict__ w2, const float* __restrict__ b2,
    const float* __restrict__ w3, const float* __restrict__ b3,
    float* __restrict__ out)
{
    __shared__ __align__(16) float s_w1[HID * HID];   // 16 KB (w1 rows 0..63)
    __shared__ __align__(16) float s_w2[HID * HID];   // 16 KB
    __shared__ __align__(16) float s_x[JPB * XS];     // 2.1 KB (x, then t)
    __shared__ float s_bp[4][HID];
    __shared__ float s_base[HID];
    __shared__ float s_red[JJ];
    __shared__ int   s_ticket;

    const int tid  = threadIdx.x;
    const int bb   = blockIdx.x >> 4;                 // batch
    const int jb0  = (blockIdx.x & 15) * JPB;         // first job of this block
    const int job  = tid >> 5;                        // 0..7 (warp = job)
    const int lane = tid & 31;
    const int h0   = lane * 2;                        // 0,2,..,62

    // ---- load weights to smem (coalesced float4) ----
    {
        const float4* w1v = (const float4*)w1;        // rows 0..63 contiguous
        const float4* w2v = (const float4*)w2;
        float4* d1 = (float4*)s_w1; float4* d2 = (float4*)s_w2;
        #pragma unroll
        for (int i = 0; i < 4; i++) {
            d1[tid + 256 * i] = w1v[tid + 256 * i];
            d2[tid + 256 * i] = w2v[tid + 256 * i];
        }
    }

    // ---- batch-invariant base: b1 + gge@w1[64:128] + pmi@w1[128:192] ----
    {
        const int q = tid >> 6, h = tid & 63;
        const float* xs = (q < 2) ? (g_gge + bb * HID) : pmi;
        const int f0 = (q & 1) * 32;
        const int row0 = 64 + (q >> 1) * 64 + f0;
        float a = 0.f;
        #pragma unroll 8
        for (int i = 0; i < 32; i++)
            a += xs[f0 + i] * w1[(row0 + i) * HID + h];
        s_bp[q][h] = a;
    }

    // ---- gather candidate embeddings into s_x ----
    {
        const int c = cand[bb * JJ + jb0 + job];
        const float2* e2 = (const float2*)(g_h2 + ((size_t)bb * NN + c) * HID);
        *(float2*)&s_x[job * XS + h0] = e2[lane];
    }
    if (tid == 0) s_ticket = -1;
    __syncthreads();

    if (tid < HID)
        s_base[tid] = b1[tid] + ((s_bp[0][tid] + s_bp[1][tid])
                               + (s_bp[2][tid] + s_bp[3][tid]));
    __syncthreads();

    // ---- layer 1: t = tanh(base + emb @ w1[0:64]) ----
    float a0 = s_base[h0], a1 = s_base[h0 + 1];
    #pragma unroll 16
    for (int f = 0; f < HID; f++) {
        const float xv = s_x[job * XS + f];
        const float2 wv = *(const float2*)&s_w1[f * HID + h0];
        a0 += xv * wv.x; a1 += xv * wv.y;
    }
    __syncthreads();                      // all x reads done
    s_x[job * XS + h0]     = tanhf(a0);
    s_x[job * XS + h0 + 1] = tanhf(a1);
    __syncthreads();

    // ---- layer 2: c = tanh(t @ w2 + b2) ----
    a0 = b2[h0]; a1 = b2[h0 + 1];
    #pragma unroll 16
    for (int f = 0; f < HID; f++) {
        const float tv = s_x[job * XS + f];
        const float2 wv = *(const float2*)&s_w2[f * HID + h0];
        a0 += tv * wv.x; a1 += tv * wv.y;
    }

    // ---- layer 3 + mask ----
    float part = tanhf(a0) * w3[h0] + tanhf(a1) * w3[h0 + 1];
    #pragma unroll
    for (int o = 16; o > 0; o >>= 1)
        part += __shfl_down_sync(0xffffffffu, part, o);
    if (lane == 0) {
        const int jg = jb0 + job;
        float score = (part + b3[0]) * 10.0f;
        if (mask[bb * JJ + jg]) score = -INFINITY;
        g_scores[bb * JJ + jg] = score;
        __threadfence();
    }
    __syncthreads();
    if (tid == 0) s_ticket = atomicAdd(&g_done[bb], 1);
    __syncthreads();

    if (s_ticket == 15) {                 // last of 16 blocks for this batch
        __threadfence();
        const float sc = (tid < JJ) ? __ldcg(&g_scores[bb * JJ + tid]) : -INFINITY;
        if (tid < JJ) s_red[tid] = sc;
        __syncthreads();
        for (int s = JJ / 2; s > 0; s >>= 1) {
            if (tid < s) s_red[tid] = fmaxf(s_red[tid], s_red[tid + s]);
            __syncthreads();
        }
        const float mx = s_red[0]; __syncthreads();
        const float e = (tid < JJ) ? expf(sc - mx) : 0.f;
        if (tid < JJ) s_red[tid] = e;
        __syncthreads();
        for (int s = JJ / 2; s > 0; s >>= 1) {
            if (tid < s) s_red[tid] += s_red[tid + s];
            __syncthreads();
        }
        if (tid < JJ) out[bb * JJ + tid] = e / s_red[0];
    }
}

// ============================================================================
extern "C" void kernel_launch(void* const* d_in, const int* in_sizes, int n_in,
                              void* d_out, int out_size)
{
    const float* features   = (const float*)d_in[0];
    const float* graph_pool = (const float*)d_in[1];
    const float* adj        = (const float*)d_in[2];
    const int*   candidate  = (const int*)d_in[3];
    const int*   mask       = (const int*)d_in[4];
    const float* g0w1 = (const float*)d_in[5];
    const float* g0b1 = (const float*)d_in[6];
    const float* g0w2 = (const float*)d_in[7];
    const float* g0b2 = (const float*)d_in[8];
    const float* g1w1 = (const float*)d_in[9];
    const float* g1b1 = (const float*)d_in[10];
    const float* g1w2 = (const float*)d_in[11];
    const float* g1b2 = (const float*)d_in[12];
    const float* pmi  = (const float*)d_in[13];
    const float* aw1  = (const float*)d_in[14];
    const float* ab1  = (const float*)d_in[15];
    const float* aw2  = (const float*)d_in[16];
    const float* ab2  = (const float*)d_in[17];
    const float* aw3  = (const float*)d_in[18];
    const float* ab3  = (const float*)d_in[19];
    float* out = (float*)d_out;

    k1_scan<<<NROWS / 16, 512>>>(adj, features, g0w1, g0b1, g0w2, g0b2);
    k2a_gather<<<NROWS / 32, 256>>>();
    k2b_mlp<<<NROWS / NPB, 256>>>(g1w1, g1b1, g1w2, g1b2, graph_pool);
    k3_actor<<<BB * JJ / JPB, 256>>>(candidate, mask, pmi,
                                     aw1, ab1, aw2, ab2, aw3, ab3, out);
}

// round 11
// speedup vs baseline: 1.5443x; 1.0554x over previous
#include <cuda_runtime.h>
#include <cstdint>
#include <math.h>

#define BB   8
#define NN   4096
#define HID  64
#define JJ   128
#define CAP  96
#define NROWS (BB*NN)   // 32768

// ---- scratch (device globals; no allocation allowed) ----
__device__ int   g_cnt[NROWS];
__device__ int   g_idx[(size_t)NROWS * CAP];   // packed: col | (val==2 ? 0x80000000 : 0)
__device__ float g_h1[(size_t)NROWS * HID];    // 8 MB
__device__ float g_h2[(size_t)NROWS * HID];    // 8 MB
__device__ float g_gge[BB * HID];              // global graph embedding accumulator
__device__ float g_scores[BB * JJ];            // actor scores before softmax
__device__ int   g_done[BB];                   // per-batch completion counters

__device__ __forceinline__ void cp_async16(void* smem_dst, const void* gmem_src) {
    unsigned sa = (unsigned)__cvta_generic_to_shared(smem_dst);
    asm volatile("cp.async.cg.shared.global [%0], [%1], 16;\n"
                 :: "r"(sa), "l"(gmem_src));
}
__device__ __forceinline__ void cp_commit() {
    asm volatile("cp.async.commit_group;\n");
}
template <int N>
__device__ __forceinline__ void cp_wait() {
    asm volatile("cp.async.wait_group %0;\n" :: "n"(N));
}
__device__ __forceinline__ float tanh_fast(float x) {
    float r;
    asm("tanh.approx.f32 %0, %1;" : "=f"(r) : "f"(x));
    return r;
}

// ============================================================================
// Kernel 1 (UNCHANGED, at HBM wall): stream adj once via per-warp cp.async
// ring. Warp-per-row, group-skip, shared-atomic compaction + GIN0 MLP.
// ============================================================================
#define NBUF 3
#define NCHUNK 32
__global__ __launch_bounds__(512) void k1_scan(
    const float* __restrict__ adj, const float* __restrict__ feat,
    const float* __restrict__ w1, const float* __restrict__ b1,
    const float* __restrict__ w2, const float* __restrict__ b2)
{
    __shared__ float s_w2[HID * HID];
    __shared__ uint4 s_buf[16][NBUF][32];
    __shared__ float s_w1[2 * HID];
    __shared__ float s_b1[HID], s_b2[HID];
    __shared__ float s_p[16][2];
    __shared__ float s_z[16][HID];
    __shared__ int   s_cnt[16];

    const int tid  = threadIdx.x;
    const int w    = tid >> 5;
    const int lane = tid & 31;

    for (int i = tid; i < HID * HID; i += 512) s_w2[i] = w2[i];
    if (tid < 2 * HID) s_w1[tid] = w1[tid];
    if (tid < HID) { s_b1[tid] = b1[tid]; s_b2[tid] = b2[tid]; }
    if (lane == 0) s_cnt[w] = 0;
    if (blockIdx.x == 0) {
        if (tid < BB * HID) g_gge[tid] = 0.f;
        if (tid < BB) g_done[tid] = 0;
    }
    __syncwarp();

    const int r = blockIdx.x * 16 + w;
    const int b = r >> 12;
    const float* __restrict__ grow = adj + (size_t)r * NN;
    const float2* __restrict__ f2p = (const float2*)feat + (size_t)b * NN;
    int* __restrict__ irow = g_idx + (size_t)r * CAP;

    float p0 = 0.f, p1 = 0.f;

#define PROC_ELEM(bits, jj) do {                                           \
        if ((bits) != 0u) {                                                \
            const int pos = atomicAdd(&s_cnt[w], 1);                       \
            const bool two = ((bits) == 0x40000000u);                      \
            if (pos < CAP) irow[pos] = (jj) | (two ? 0x80000000 : 0);      \
            const float2 f = f2p[(jj)];                                    \
            const float sv = two ? 2.f : 1.f;                              \
            p0 += sv * f.x; p1 += sv * f.y;                                \
        }                                                                  \
    } while (0)

#define PROC_CHUNK(c) do {                                                 \
        const uint4 v = s_buf[w][(c) % NBUF][lane];                        \
        if (v.x | v.y | v.z | v.w) {                                       \
            const int jb = (c) * 128 + lane * 4;                           \
            PROC_ELEM(v.x, jb + 0);                                        \
            PROC_ELEM(v.y, jb + 1);                                        \
            PROC_ELEM(v.z, jb + 2);                                        \
            PROC_ELEM(v.w, jb + 3);                                        \
        }                                                                  \
    } while (0)

    #pragma unroll
    for (int c = 0; c < NBUF; c++) {
        cp_async16(&s_buf[w][c][lane], grow + c * 128 + lane * 4);
        cp_commit();
    }
    #pragma unroll 1
    for (int c = 0; c < NCHUNK - NBUF; c++) {
        cp_wait<NBUF - 1>();
        PROC_CHUNK(c);
        cp_async16(&s_buf[w][(c + NBUF) % NBUF][lane],
                   grow + (c + NBUF) * 128 + lane * 4);
        cp_commit();
    }
    cp_wait<0>();
    #pragma unroll
    for (int c = NCHUNK - NBUF; c < NCHUNK; c++) PROC_CHUNK(c);
#undef PROC_CHUNK
#undef PROC_ELEM

    #pragma unroll
    for (int o = 16; o > 0; o >>= 1) {
        p0 += __shfl_down_sync(0xffffffffu, p0, o);
        p1 += __shfl_down_sync(0xffffffffu, p1, o);
    }
    __syncwarp();
    if (lane == 0) {
        s_p[w][0] = p0; s_p[w][1] = p1;
        g_cnt[r] = min(s_cnt[w], CAP);
    }
    __syncthreads();

    const int h = tid & 63;
    const int slot = tid >> 6;
    #pragma unroll
    for (int t = 0; t < 2; t++) {
        const int rr = slot + t * 8;
        const float z = s_b1[h] + s_p[rr][0] * s_w1[h] + s_p[rr][1] * s_w1[HID + h];
        s_z[rr][h] = fmaxf(z, 0.f);
    }
    __syncthreads();
    #pragma unroll
    for (int t = 0; t < 2; t++) {
        const int rr = slot + t * 8;
        float acc = s_b2[h];
        #pragma unroll
        for (int k = 0; k < HID; k++) acc += s_z[rr][k] * s_w2[k * HID + h];
        g_h1[(size_t)(blockIdx.x * 16 + rr) * HID + h] = fmaxf(acc, 0.f);
    }
}

// ============================================================================
// Kernel 2 (FUSED k2a+k2b): 64 nodes / 256-thread block (512 blocks).
//   Phase A: 8 warps x 4 nodes interleaved gather, two passes, into s_x.
//   Phase B: register-stationary GIN1 MLP (weights loaded AFTER gather to
//   keep gather-phase register pressure low) + fused graph pooling.
// ============================================================================
#define NPB 64
#define BATCH 16
__global__ __launch_bounds__(256) void k2_fused(
    const float* __restrict__ w1, const float* __restrict__ b1,
    const float* __restrict__ w2, const float* __restrict__ b2,
    const float* __restrict__ gp)
{
    __shared__ __align__(16) float s_x[NPB][HID];          // 16 KB
    __shared__ __align__(16) float s_part[4][BATCH][HID];  // 16 KB
    __shared__ __align__(16) float s_z[BATCH][HID];        // 4 KB
    __shared__ float s_acc[HID];

    const int tid  = threadIdx.x;
    const int h    = tid & 63;
    const int fg   = tid >> 6;           // 0..3
    const int wid  = tid >> 5, lane = tid & 31;
    const int base = blockIdx.x * NPB;
    const int b    = base >> 12;
    const float2* __restrict__ h1v = (const float2*)g_h1 + ((size_t)b << 12) * 32;

    if (tid < HID) s_acc[tid] = 0.f;

    // ---- Phase A: gather 64 nodes (two passes of 8 warps x 4 nodes) ----
    #pragma unroll 1
    for (int pass = 0; pass < 2; pass++) {
        const int ln0 = wid * 4 + pass * 32;
        int cnt[4]; const int* ip[4];
        #pragma unroll
        for (int i = 0; i < 4; i++) {
            cnt[i] = g_cnt[base + ln0 + i];
            ip[i]  = g_idx + (size_t)(base + ln0 + i) * CAP;
        }
        float ax[4] = {0.f, 0.f, 0.f, 0.f}, ay[4] = {0.f, 0.f, 0.f, 0.f};
        const int maxc = max(max(cnt[0], cnt[1]), max(cnt[2], cnt[3]));
        for (int k0 = 0; k0 < maxc; k0 += 32) {
            int enc[4];
            #pragma unroll
            for (int i = 0; i < 4; i++)
                enc[i] = (k0 + lane < cnt[i]) ? ip[i][k0 + lane] : 0;
            const int rem = min(maxc - k0, 32);
            #pragma unroll 2
            for (int n = 0; n < rem; n++) {
                #pragma unroll
                for (int i = 0; i < 4; i++) {
                    const int e = __shfl_sync(0xffffffffu, enc[i], n);
                    if (k0 + n < cnt[i]) {       // warp-uniform predicate
                        const float2 v = h1v[(size_t)(e & 0x7fffffff) * 32 + lane];
                        const float s = (e < 0) ? 2.f : 1.f;
                        ax[i] += s * v.x; ay[i] += s * v.y;
                    }
                }
            }
        }
        #pragma unroll
        for (int i = 0; i < 4; i++)
            *(float2*)&s_x[ln0 + i][2 * lane] = make_float2(ax[i], ay[i]);
    }

    // ---- load register-stationary weights (after gather: low reg overlap) ----
    float w1r[16], w2r[16];
    #pragma unroll
    for (int i = 0; i < 16; i++) {
        w1r[i] = w1[(fg * 16 + i) * HID + h];
        w2r[i] = w2[(fg * 16 + i) * HID + h];
    }
    __syncthreads();

    // ---- Phase B: MLP over 4 batches of 16 nodes ----
    float gacc = 0.f;
    #pragma unroll 1
    for (int nb = 0; nb < 4; nb++) {
        const int n0 = nb * BATCH;

        // layer 1 partials
        #pragma unroll
        for (int n = 0; n < BATCH; n++) {
            float a = 0.f;
            #pragma unroll
            for (int q = 0; q < 4; q++) {
                const float4 xv = *(const float4*)&s_x[n0 + n][fg * 16 + q * 4];
                a += xv.x * w1r[q * 4] + xv.y * w1r[q * 4 + 1]
                   + xv.z * w1r[q * 4 + 2] + xv.w * w1r[q * 4 + 3];
            }
            s_part[fg][n][h] = a;
        }
        __syncthreads();

        // reduce + bias + relu -> z
        #pragma unroll
        for (int k = 0; k < 4; k++) {
            const int p = tid + 256 * k;
            const int n = p >> 6, hh = p & 63;
            const float z = b1[hh] + ((s_part[0][n][hh] + s_part[1][n][hh])
                                    + (s_part[2][n][hh] + s_part[3][n][hh]));
            s_z[n][hh] = fmaxf(z, 0.f);
        }
        __syncthreads();

        // layer 2 partials
        #pragma unroll
        for (int n = 0; n < BATCH; n++) {
            float a = 0.f;
            #pragma unroll
            for (int q = 0; q < 4; q++) {
                const float4 zv = *(const float4*)&s_z[n][fg * 16 + q * 4];
                a += zv.x * w2r[q * 4] + zv.y * w2r[q * 4 + 1]
                   + zv.z * w2r[q * 4 + 2] + zv.w * w2r[q * 4 + 3];
            }
            s_part[fg][n][h] = a;
        }
        __syncthreads();

        // reduce + bias + relu -> h2 (gmem) + pooling (hh == h for all k)
        #pragma unroll
        for (int k = 0; k < 4; k++) {
            const int p = tid + 256 * k;
            const int n = p >> 6, hh = p & 63;
            float v = b2[hh] + ((s_part[0][n][hh] + s_part[1][n][hh])
                              + (s_part[2][n][hh] + s_part[3][n][hh]));
            v = fmaxf(v, 0.f);
            g_h2[(size_t)(base + n0 + n) * HID + hh] = v;
            gacc += gp[base + n0 + n] * v;
        }
        __syncthreads();                 // s_part reuse next batch
    }
    atomicAdd(&s_acc[h], gacc);
    __syncthreads();
    if (tid < HID) atomicAdd(&g_gge[b * HID + tid], s_acc[tid]);
}

// ============================================================================
// Kernel 3: 128 blocks x 256 threads; block = (batch, 8 jobs).
//   cp.async weight staging overlapped with base matvec + candidate gather;
//   tanh.approx.f32; ticket softmax (16 blocks/batch).
// ============================================================================
#define JPB 8
#define XS  66   // padded stride for x/t rows
__global__ __launch_bounds__(256) void k3_actor(
    const int* __restrict__ cand, const int* __restrict__ mask,
    const float* __restrict__ pmi,
    const float* __restrict__ w1, const float* __restrict__ b1,
    const float* __restrict__ w2, const float* __restrict__ b2,
    const float* __restrict__ w3, const float* __restrict__ b3,
    float* __restrict__ out)
{
    __shared__ __align__(16) float s_w1[HID * HID];   // 16 KB (w1 rows 0..63)
    __shared__ __align__(16) float s_w2[HID * HID];   // 16 KB
    __shared__ __align__(16) float s_x[JPB * XS];     // 2.1 KB (x, then t)
    __shared__ float s_bp[4][HID];
    __shared__ float s_base[HID];
    __shared__ float s_red[JJ];
    __shared__ int   s_ticket;

    const int tid  = threadIdx.x;
    const int bb   = blockIdx.x >> 4;                 // batch
    const int jb0  = (blockIdx.x & 15) * JPB;         // first job of this block
    const int job  = tid >> 5;                        // 0..7 (warp = job)
    const int lane = tid & 31;
    const int h0   = lane * 2;                        // 0,2,..,62

    // ---- stage weights via cp.async (latency overlapped with work below) ----
    {
        const float4* w1v = (const float4*)w1;        // rows 0..63 contiguous
        const float4* w2v = (const float4*)w2;
        float4* d1 = (float4*)s_w1; float4* d2 = (float4*)s_w2;
        #pragma unroll
        for (int i = 0; i < 4; i++) {
            cp_async16(&d1[tid + 256 * i], &w1v[tid + 256 * i]);
            cp_async16(&d2[tid + 256 * i], &w2v[tid + 256 * i]);
        }
        cp_commit();
    }

    // ---- batch-invariant base: b1 + gge@w1[64:128] + pmi@w1[128:192] ----
    {
        const int q = tid >> 6, h = tid & 63;
        const float* xs = (q < 2) ? (g_gge + bb * HID) : pmi;
        const int f0 = (q & 1) * 32;
        const int row0 = 64 + (q >> 1) * 64 + f0;
        float a = 0.f;
        #pragma unroll 8
        for (int i = 0; i < 32; i++)
            a += xs[f0 + i] * w1[(row0 + i) * HID + h];
        s_bp[q][h] = a;
    }

    // ---- gather candidate embeddings into s_x ----
    {
        const int c = cand[bb * JJ + jb0 + job];
        const float2* e2 = (const float2*)(g_h2 + ((size_t)bb * NN + c) * HID);
        *(float2*)&s_x[job * XS + h0] = e2[lane];
    }
    if (tid == 0) s_ticket = -1;
    cp_wait<0>();                         // weight staging landed (this thread)
    __syncthreads();

    if (tid < HID)
        s_base[tid] = b1[tid] + ((s_bp[0][tid] + s_bp[1][tid])
                               + (s_bp[2][tid] + s_bp[3][tid]));
    __syncthreads();

    // ---- layer 1: t = tanh(base + emb @ w1[0:64]) ----
    float a0 = s_base[h0], a1 = s_base[h0 + 1];
    #pragma unroll 16
    for (int f = 0; f < HID; f++) {
        const float xv = s_x[job * XS + f];
        const float2 wv = *(const float2*)&s_w1[f * HID + h0];
        a0 += xv * wv.x; a1 += xv * wv.y;
    }
    __syncthreads();                      // all x reads done
    s_x[job * XS + h0]     = tanh_fast(a0);
    s_x[job * XS + h0 + 1] = tanh_fast(a1);
    __syncthreads();

    // ---- layer 2: c = tanh(t @ w2 + b2) ----
    a0 = b2[h0]; a1 = b2[h0 + 1];
    #pragma unroll 16
    for (int f = 0; f < HID; f++) {
        const float tv = s_x[job * XS + f];
        const float2 wv = *(const float2*)&s_w2[f * HID + h0];
        a0 += tv * wv.x; a1 += tv * wv.y;
    }

    // ---- layer 3 + mask ----
    float part = tanh_fast(a0) * w3[h0] + tanh_fast(a1) * w3[h0 + 1];
    #pragma unroll
    for (int o = 16; o > 0; o >>= 1)
        part += __shfl_down_sync(0xffffffffu, part, o);
    if (lane == 0) {
        const int jg = jb0 + job;
        float score = (part + b3[0]) * 10.0f;
        if (mask[bb * JJ + jg]) score = -INFINITY;
        g_scores[bb * JJ + jg] = score;
        __threadfence();
    }
    __syncthreads();
    if (tid == 0) s_ticket = atomicAdd(&g_done[bb], 1);
    __syncthreads();

    if (s_ticket == 15) {                 // last of 16 blocks for this batch
        __threadfence();
        const float sc = (tid < JJ) ? __ldcg(&g_scores[bb * JJ + tid]) : -INFINITY;
        if (tid < JJ) s_red[tid] = sc;
        __syncthreads();
        for (int s = JJ / 2; s > 0; s >>= 1) {
            if (tid < s) s_red[tid] = fmaxf(s_red[tid], s_red[tid + s]);
            __syncthreads();
        }
        const float mx = s_red[0]; __syncthreads();
        const float e = (tid < JJ) ? expf(sc - mx) : 0.f;
        if (tid < JJ) s_red[tid] = e;
        __syncthreads();
        for (int s = JJ / 2; s > 0; s >>= 1) {
            if (tid < s) s_red[tid] += s_red[tid + s];
            __syncthreads();
        }
        if (tid < JJ) out[bb * JJ + tid] = e / s_red[0];
    }
}

// ============================================================================
extern "C" void kernel_launch(void* const* d_in, const int* in_sizes, int n_in,
                              void* d_out, int out_size)
{
    const float* features   = (const float*)d_in[0];
    const float* graph_pool = (const float*)d_in[1];
    const float* adj        = (const float*)d_in[2];
    const int*   candidate  = (const int*)d_in[3];
    const int*   mask       = (const int*)d_in[4];
    const float* g0w1 = (const float*)d_in[5];
    const float* g0b1 = (const float*)d_in[6];
    const float* g0w2 = (const float*)d_in[7];
    const float* g0b2 = (const float*)d_in[8];
    const float* g1w1 = (const float*)d_in[9];
    const float* g1b1 = (const float*)d_in[10];
    const float* g1w2 = (const float*)d_in[11];
    const float* g1b2 = (const float*)d_in[12];
    const float* pmi  = (const float*)d_in[13];
    const float* aw1  = (const float*)d_in[14];
    const float* ab1  = (const float*)d_in[15];
    const float* aw2  = (const float*)d_in[16];
    const float* ab2  = (const float*)d_in[17];
    const float* aw3  = (const float*)d_in[18];
    const float* ab3  = (const float*)d_in[19];
    float* out = (float*)d_out;

    k1_scan<<<NROWS / 16, 512>>>(adj, features, g0w1, g0b1, g0w2, g0b2);
    k2_fused<<<NROWS / NPB, 256>>>(g1w1, g1b1, g1w2, g1b2, graph_pool);
    k3_actor<<<BB * JJ / JPB, 256>>>(candidate, mask, pmi,
                                     aw1, ab1, aw2, ab2, aw3, ab3, out);
}